// round 2
// baseline (speedup 1.0000x reference)
#include <cuda_runtime.h>

// ---------------------------------------------------------------------------
// SimpleCNN gated pipeline, fp32 baseline.
// Stage kernels:
//   k_conv1 : masks m1,m2 + conv1(1->32,pad1) gated + relu + maxpool2 gated -> g_p1 [256][32][32][32]
//   k_conv2 : masks m3,m4 + conv2(32->64,pad1) gated + relu + maxpool2 gated -> g_p2 [256][64][16][16]
//   k_fc1   : split-K GEMM partials of p2_flat @ Wfc1^T -> g_part
//   k_fc2   : reduce partials + bfc1 + relu + FC2 -> out [256][10]
// ---------------------------------------------------------------------------

#define NB 256

__device__ float          g_p1[NB * 32 * 32 * 32];   // 33.5 MB
__device__ unsigned char  g_m2[NB * 32 * 32];
__device__ float          g_p2[NB * 64 * 16 * 16];   // 16.8 MB
__device__ float          g_part[64 * NB * 128];     // 8.4 MB split-K partials

// ===========================================================================
// Kernel 1: conv1 + gates + pool.  One block per batch, 256 threads.
// ===========================================================================
__global__ __launch_bounds__(256) void k_conv1(
    const float* __restrict__ x, const int* __restrict__ cmap,
    const float* __restrict__ W1, const float* __restrict__ b1)
{
    __shared__ float xs[66 * 66];          // zero-padded input
    __shared__ unsigned char cs[64 * 64];
    __shared__ unsigned char rs[64 * 64];  // horizontal 3-sum of c
    __shared__ unsigned char m1s[64 * 64];
    __shared__ unsigned char m2s[32 * 32];
    __shared__ float w1s[288];
    __shared__ float b1s[32];

    const int b = blockIdx.x, t = threadIdx.x;
    const float* xb = x + b * 4096;
    const int*   cb = cmap + b * 4096;

    for (int i = t; i < 66 * 66; i += 256) {
        int r = i / 66, c = i % 66;
        float v = 0.f;
        if (r >= 1 && r <= 64 && c >= 1 && c <= 64) v = xb[(r - 1) * 64 + (c - 1)];
        xs[i] = v;
    }
    for (int i = t; i < 4096; i += 256) cs[i] = (unsigned char)cb[i];
    for (int i = t; i < 288; i += 256) w1s[i] = W1[i];     // FIX: was `if (t < 288)` with 256 threads
    if (t < 32)  b1s[t] = b1[t];
    __syncthreads();

    // rs[i][j] = c[i][j] + c[i][j+1] + c[i][j+2]  (clamped right)
    for (int i = t; i < 4096; i += 256) {
        int c = i & 63;
        int s = cs[i];
        if (c < 63) s += cs[i + 1];
        if (c < 62) s += cs[i + 2];
        rs[i] = (unsigned char)s;
    }
    __syncthreads();
    // m1[i][j] = win3 sum > 1
    for (int i = t; i < 4096; i += 256) {
        int r = i >> 6;
        int s = rs[i];
        if (r < 63) s += rs[i + 64];
        if (r < 62) s += rs[i + 128];
        m1s[i] = (unsigned char)(s > 1);
    }
    __syncthreads();
    // m2 = 2x2 pool-sum of m1 > 1
    for (int i = t; i < 1024; i += 256) {
        int r = i >> 5, c = i & 31;
        int s = m1s[(2 * r) * 64 + 2 * c] + m1s[(2 * r) * 64 + 2 * c + 1]
              + m1s[(2 * r + 1) * 64 + 2 * c] + m1s[(2 * r + 1) * 64 + 2 * c + 1];
        m2s[i] = (unsigned char)(s > 1);
    }
    __syncthreads();
    for (int i = t; i < 1024; i += 256) g_m2[b * 1024 + i] = m2s[i];

    float* p1b = g_p1 + b * 32768;   // [ci][32][32]

    for (int pp = 0; pp < 4; pp++) {
        const int pos = pp * 256 + t;
        const int py = pos >> 5, px = pos & 31;
        const bool g2 = (m2s[pos] != 0);

        float patch[4][4];
        #pragma unroll
        for (int r = 0; r < 4; r++)
            #pragma unroll
            for (int c = 0; c < 4; c++)
                patch[r][c] = xs[(2 * py + r) * 66 + (2 * px + c)];

        bool mm[2][2];
        mm[0][0] = m1s[(2 * py) * 64 + 2 * px];
        mm[0][1] = m1s[(2 * py) * 64 + 2 * px + 1];
        mm[1][0] = m1s[(2 * py + 1) * 64 + 2 * px];
        mm[1][1] = m1s[(2 * py + 1) * 64 + 2 * px + 1];

        for (int co = 0; co < 32; co++) {
            float best = 0.f;
            if (g2) {
                float wv[9];
                #pragma unroll
                for (int k = 0; k < 9; k++) wv[k] = w1s[co * 9 + k];
                const float bias = b1s[co];
                #pragma unroll
                for (int dr = 0; dr < 2; dr++)
                    #pragma unroll
                    for (int dc = 0; dc < 2; dc++) {
                        if (mm[dr][dc]) {
                            float s = bias;
                            #pragma unroll
                            for (int kr = 0; kr < 3; kr++)
                                #pragma unroll
                                for (int kc = 0; kc < 3; kc++)
                                    s += wv[kr * 3 + kc] * patch[dr + kr][dc + kc];
                            best = fmaxf(best, s);   // relu + pool (gated-off entries are 0)
                        }
                    }
            }
            p1b[co * 1024 + pos] = best;   // coalesced across warp
        }
    }
}

// ===========================================================================
// Kernel 2: conv2 + gates + pool.  One block per batch, 256 threads.
// Dynamic smem: ps[32][34][36] padded input, W2 half, masks.
// Thread = (co-group of 8 per half) x (4x4 pre-pool patch -> 2x2 pooled outs)
// ===========================================================================
#define PS_STRIDE_ROW 36
#define PS_STRIDE_CH  (34 * 36)
#define SMEM_PS_F     (32 * 34 * 36)          // 39168 floats
#define SMEM_W2_F     (32 * 32 * 9)           // 9216 floats (one half of W2)
#define SMEM_C2_BYTES ((SMEM_PS_F + SMEM_W2_F + 64) * 4 + 1024 + 1024 + 256)

__global__ __launch_bounds__(256) void k_conv2(
    const float* __restrict__ W2, const float* __restrict__ b2)
{
    extern __shared__ float sm[];
    float* ps  = sm;
    float* w2s = sm + SMEM_PS_F;
    float* b2s = sm + SMEM_PS_F + SMEM_W2_F;
    unsigned char* m2s = (unsigned char*)(sm + SMEM_PS_F + SMEM_W2_F + 64);
    unsigned char* m3s = m2s + 1024;
    unsigned char* m4s = m3s + 1024;

    const int b = blockIdx.x, t = threadIdx.x;

    for (int i = t; i < SMEM_PS_F; i += 256) ps[i] = 0.f;   // zero padding borders
    if (t < 64) b2s[t] = b2[t];
    for (int i = t; i < 1024; i += 256) m2s[i] = g_m2[b * 1024 + i];
    __syncthreads();

    const float* p1b = g_p1 + b * 32768;
    for (int i = t; i < 32768; i += 256) {
        int ci = i >> 10, y = (i >> 5) & 31, xx = i & 31;
        ps[ci * PS_STRIDE_CH + (y + 1) * PS_STRIDE_ROW + (xx + 1)] = p1b[i];
    }
    // m3 = win3 sum of m2 > 1 (clamped bottom/right)
    for (int i = t; i < 1024; i += 256) {
        int r = i >> 5, c = i & 31;
        int s = 0;
        #pragma unroll
        for (int dr = 0; dr < 3; dr++) {
            int rr = r + dr;
            if (rr < 32) {
                s += m2s[rr * 32 + c];
                if (c + 1 < 32) s += m2s[rr * 32 + c + 1];
                if (c + 2 < 32) s += m2s[rr * 32 + c + 2];
            }
        }
        m3s[i] = (unsigned char)(s > 1);
    }
    __syncthreads();
    // m4 = 2x2 pool-sum of m3 > 1
    for (int i = t; i < 256; i += 256) {
        int r = i >> 4, c = i & 15;
        int s = m3s[(2 * r) * 32 + 2 * c] + m3s[(2 * r) * 32 + 2 * c + 1]
              + m3s[(2 * r + 1) * 32 + 2 * c] + m3s[(2 * r + 1) * 32 + 2 * c + 1];
        m4s[i] = (unsigned char)(s > 1);
    }
    __syncthreads();

    const int cg  = t >> 6;        // 0..3  (warps 0-1 -> cg0, ... : broadcast weight loads)
    const int sp  = t & 63;        // 64 spatial threads: 8x8 grid of 2x2-pooled blocks
    const int pby = sp >> 3, pbx = sp & 7;
    const int r0  = 4 * pby, c0 = 4 * pbx;   // padded-smem coords of 6x6 patch origin

    float* p2b = g_p2 + b * 16384;   // [co][16][16]

    for (int half = 0; half < 2; half++) {
        __syncthreads();   // previous compute done before w2s overwrite
        for (int i = t; i < SMEM_W2_F; i += 256) w2s[i] = W2[half * SMEM_W2_F + i];
        __syncthreads();

        #pragma unroll
        for (int tile = 0; tile < 2; tile++) {
            const int co0 = cg * 8 + tile * 4;   // local co within half

            float acc[4][16];
            #pragma unroll
            for (int q = 0; q < 4; q++)
                #pragma unroll
                for (int p = 0; p < 16; p++) acc[q][p] = 0.f;

            for (int ci = 0; ci < 32; ci++) {
                float patch[6][6];
                #pragma unroll
                for (int r = 0; r < 6; r++) {
                    const float* row = ps + ci * PS_STRIDE_CH + (r0 + r) * PS_STRIDE_ROW + c0;
                    float4 v4 = *(const float4*)row;          // 16B-aligned (c0 % 4 == 0)
                    float2 v2 = *(const float2*)(row + 4);
                    patch[r][0] = v4.x; patch[r][1] = v4.y; patch[r][2] = v4.z;
                    patch[r][3] = v4.w; patch[r][4] = v2.x; patch[r][5] = v2.y;
                }
                #pragma unroll
                for (int q = 0; q < 4; q++) {
                    const float* w = w2s + (co0 + q) * 288 + ci * 9;  // warp-broadcast
                    #pragma unroll
                    for (int kr = 0; kr < 3; kr++)
                        #pragma unroll
                        for (int kc = 0; kc < 3; kc++) {
                            const float wv = w[kr * 3 + kc];
                            #pragma unroll
                            for (int lr = 0; lr < 4; lr++)
                                #pragma unroll
                                for (int lc = 0; lc < 4; lc++)
                                    acc[q][lr * 4 + lc] += wv * patch[lr + kr][lc + kc];
                        }
                }
            }

            // gate m3 -> +bias -> relu -> pool -> gate m4 -> store
            #pragma unroll
            for (int q = 0; q < 4; q++) {
                const int co = half * 32 + co0 + q;
                const float bias = b2s[co];
                #pragma unroll
                for (int qy = 0; qy < 2; qy++)
                    #pragma unroll
                    for (int qx = 0; qx < 2; qx++) {
                        const int gy = 2 * pby + qy, gx = 2 * pbx + qx;
                        float best = 0.f;
                        if (m4s[gy * 16 + gx]) {
                            #pragma unroll
                            for (int dr = 0; dr < 2; dr++)
                                #pragma unroll
                                for (int dc = 0; dc < 2; dc++) {
                                    const int yy = 2 * gy + dr, xx = 2 * gx + dc; // 0..31
                                    if (m3s[yy * 32 + xx]) {
                                        float v = acc[q][(2 * qy + dr) * 4 + (2 * qx + dc)] + bias;
                                        best = fmaxf(best, v);
                                    }
                                }
                        }
                        p2b[co * 256 + gy * 16 + gx] = best;
                    }
            }
        }
    }
}

// ===========================================================================
// Kernel 3: FC1 split-K GEMM partials.  C[256,128] = p2_flat[256,16384] @ Wfc1^T
// grid (KSPLIT=64, 8 batch-tiles of 32), 128 threads, thread tile 4b x 8j.
// Deterministic (no atomics): partials to g_part[ks][b][j].
// ===========================================================================
#define KSPLIT 64
#define FC1_SMEM_F (32 * 128 + 128 * 132)     // As + padded Bs
#define FC1_SMEM_BYTES (FC1_SMEM_F * 4)

__global__ __launch_bounds__(128) void k_fc1(const float* __restrict__ Wfc1)
{
    extern __shared__ float sm[];
    float* As = sm;            // [32][128]
    float* Bs = sm + 4096;     // [128][132]  (pad 132 -> conflict-light transpose store)

    const int ks = blockIdx.x, bt = blockIdx.y, t = threadIdx.x;
    const int jgrp = t & 15, bgrp = t >> 4;
    const int k0 = ks * 256;

    float acc[4][8];
    #pragma unroll
    for (int i = 0; i < 4; i++)
        #pragma unroll
        for (int j = 0; j < 8; j++) acc[i][j] = 0.f;

    for (int ch = 0; ch < 2; ch++) {
        const int kc0 = k0 + ch * 128;
        __syncthreads();
        for (int i = t; i < 4096; i += 128) {
            int bb = i >> 7, kk = i & 127;
            As[i] = g_p2[(bt * 32 + bb) * 16384 + kc0 + kk];
        }
        for (int i = t; i < 16384; i += 128) {
            int j = i >> 7, kk = i & 127;
            Bs[kk * 132 + j] = Wfc1[j * 16384 + kc0 + kk];
        }
        __syncthreads();

        #pragma unroll 4
        for (int kk = 0; kk < 128; kk++) {
            float a0 = As[(bgrp * 4 + 0) * 128 + kk];
            float a1 = As[(bgrp * 4 + 1) * 128 + kk];
            float a2 = As[(bgrp * 4 + 2) * 128 + kk];
            float a3 = As[(bgrp * 4 + 3) * 128 + kk];
            float4 v0 = *(const float4*)&Bs[kk * 132 + jgrp * 8];
            float4 v1 = *(const float4*)&Bs[kk * 132 + jgrp * 8 + 4];
            float bv[8] = {v0.x, v0.y, v0.z, v0.w, v1.x, v1.y, v1.z, v1.w};
            #pragma unroll
            for (int j = 0; j < 8; j++) {
                acc[0][j] += a0 * bv[j];
                acc[1][j] += a1 * bv[j];
                acc[2][j] += a2 * bv[j];
                acc[3][j] += a3 * bv[j];
            }
        }
    }

    #pragma unroll
    for (int i = 0; i < 4; i++) {
        const int bglob = bt * 32 + bgrp * 4 + i;
        #pragma unroll
        for (int j = 0; j < 8; j++)
            g_part[ks * (NB * 128) + bglob * 128 + jgrp * 8 + j] = acc[i][j];
    }
}

// ===========================================================================
// Kernel 4: reduce partials + bfc1 + relu, then FC2 -> out[256][10]
// ===========================================================================
__global__ __launch_bounds__(128) void k_fc2(
    const float* __restrict__ bfc1, const float* __restrict__ Wfc2,
    const float* __restrict__ bfc2, float* __restrict__ out)
{
    __shared__ float hs[128];
    const int b = blockIdx.x, t = threadIdx.x;
    float s = 0.f;
    #pragma unroll 8
    for (int ks = 0; ks < KSPLIT; ks++) s += g_part[ks * (NB * 128) + b * 128 + t];
    s += bfc1[t];
    hs[t] = fmaxf(s, 0.f);
    __syncthreads();
    if (t < 10) {
        float a = bfc2[t];
        #pragma unroll 8
        for (int j = 0; j < 128; j++) a += hs[j] * Wfc2[t * 128 + j];
        out[b * 10 + t] = a;
    }
}

// ===========================================================================
extern "C" void kernel_launch(void* const* d_in, const int* in_sizes, int n_in,
                              void* d_out, int out_size)
{
    const float* x    = (const float*)d_in[0];
    const int*   cmap = (const int*)  d_in[1];
    const float* W1   = (const float*)d_in[2];
    const float* b1   = (const float*)d_in[3];
    const float* W2   = (const float*)d_in[4];
    const float* b2   = (const float*)d_in[5];
    const float* Wfc1 = (const float*)d_in[6];
    const float* bfc1 = (const float*)d_in[7];
    const float* Wfc2 = (const float*)d_in[8];
    const float* bfc2 = (const float*)d_in[9];
    float* out = (float*)d_out;

    cudaFuncSetAttribute(k_conv2, cudaFuncAttributeMaxDynamicSharedMemorySize, SMEM_C2_BYTES);
    cudaFuncSetAttribute(k_fc1,   cudaFuncAttributeMaxDynamicSharedMemorySize, FC1_SMEM_BYTES);

    k_conv1<<<NB, 256>>>(x, cmap, W1, b1);
    k_conv2<<<NB, 256, SMEM_C2_BYTES>>>(W2, b2);
    dim3 g1(KSPLIT, 8);
    k_fc1<<<g1, 128, FC1_SMEM_BYTES>>>(Wfc1);
    k_fc2<<<NB, 128>>>(bfc1, Wfc2, bfc2, out);
}

// round 3
// speedup vs baseline: 1.0945x; 1.0945x over previous
#include <cuda_runtime.h>

// ---------------------------------------------------------------------------
// SimpleCNN gated pipeline.  R2: conv2 uses packed fma.rn.f32x2 (co-pair
// packing, weights pre-interleaved in smem); fc2 widened to 512 threads.
// ---------------------------------------------------------------------------

#define NB 256

__device__ float          g_p1[NB * 32 * 32 * 32];
__device__ unsigned char  g_m2[NB * 32 * 32];
__device__ float          g_p2[NB * 64 * 16 * 16];
__device__ float          g_part[64 * NB * 128];

typedef unsigned long long ull;

__device__ __forceinline__ ull pk2(float a, float b) {
    ull r; asm("mov.b64 %0, {%1, %2};" : "=l"(r) : "f"(a), "f"(b)); return r;
}
__device__ __forceinline__ ull fma2(ull a, ull b, ull c) {
    ull d; asm("fma.rn.f32x2 %0, %1, %2, %3;" : "=l"(d) : "l"(a), "l"(b), "l"(c)); return d;
}
__device__ __forceinline__ void upk2(ull v, float& lo, float& hi) {
    asm("mov.b64 {%0, %1}, %2;" : "=f"(lo), "=f"(hi) : "l"(v));
}

// ===========================================================================
// Kernel 1: conv1 + gates + pool.  One block per batch, 256 threads.
// ===========================================================================
__global__ __launch_bounds__(256) void k_conv1(
    const float* __restrict__ x, const int* __restrict__ cmap,
    const float* __restrict__ W1, const float* __restrict__ b1)
{
    __shared__ float xs[66 * 66];
    __shared__ unsigned char cs[64 * 64];
    __shared__ unsigned char rs[64 * 64];
    __shared__ unsigned char m1s[64 * 64];
    __shared__ unsigned char m2s[32 * 32];
    __shared__ float w1s[288];
    __shared__ float b1s[32];

    const int b = blockIdx.x, t = threadIdx.x;
    const float* xb = x + b * 4096;
    const int*   cb = cmap + b * 4096;

    for (int i = t; i < 66 * 66; i += 256) {
        int r = i / 66, c = i % 66;
        float v = 0.f;
        if (r >= 1 && r <= 64 && c >= 1 && c <= 64) v = xb[(r - 1) * 64 + (c - 1)];
        xs[i] = v;
    }
    for (int i = t; i < 4096; i += 256) cs[i] = (unsigned char)cb[i];
    for (int i = t; i < 288; i += 256) w1s[i] = W1[i];
    if (t < 32)  b1s[t] = b1[t];
    __syncthreads();

    for (int i = t; i < 4096; i += 256) {
        int c = i & 63;
        int s = cs[i];
        if (c < 63) s += cs[i + 1];
        if (c < 62) s += cs[i + 2];
        rs[i] = (unsigned char)s;
    }
    __syncthreads();
    for (int i = t; i < 4096; i += 256) {
        int r = i >> 6;
        int s = rs[i];
        if (r < 63) s += rs[i + 64];
        if (r < 62) s += rs[i + 128];
        m1s[i] = (unsigned char)(s > 1);
    }
    __syncthreads();
    for (int i = t; i < 1024; i += 256) {
        int r = i >> 5, c = i & 31;
        int s = m1s[(2 * r) * 64 + 2 * c] + m1s[(2 * r) * 64 + 2 * c + 1]
              + m1s[(2 * r + 1) * 64 + 2 * c] + m1s[(2 * r + 1) * 64 + 2 * c + 1];
        m2s[i] = (unsigned char)(s > 1);
    }
    __syncthreads();
    for (int i = t; i < 1024; i += 256) g_m2[b * 1024 + i] = m2s[i];

    float* p1b = g_p1 + b * 32768;

    for (int pp = 0; pp < 4; pp++) {
        const int pos = pp * 256 + t;
        const int py = pos >> 5, px = pos & 31;
        const bool g2 = (m2s[pos] != 0);

        float patch[4][4];
        #pragma unroll
        for (int r = 0; r < 4; r++)
            #pragma unroll
            for (int c = 0; c < 4; c++)
                patch[r][c] = xs[(2 * py + r) * 66 + (2 * px + c)];

        bool mm[2][2];
        mm[0][0] = m1s[(2 * py) * 64 + 2 * px];
        mm[0][1] = m1s[(2 * py) * 64 + 2 * px + 1];
        mm[1][0] = m1s[(2 * py + 1) * 64 + 2 * px];
        mm[1][1] = m1s[(2 * py + 1) * 64 + 2 * px + 1];

        for (int co = 0; co < 32; co++) {
            float best = 0.f;
            if (g2) {
                float wv[9];
                #pragma unroll
                for (int k = 0; k < 9; k++) wv[k] = w1s[co * 9 + k];
                const float bias = b1s[co];
                #pragma unroll
                for (int dr = 0; dr < 2; dr++)
                    #pragma unroll
                    for (int dc = 0; dc < 2; dc++) {
                        if (mm[dr][dc]) {
                            float s = bias;
                            #pragma unroll
                            for (int kr = 0; kr < 3; kr++)
                                #pragma unroll
                                for (int kc = 0; kc < 3; kc++)
                                    s += wv[kr * 3 + kc] * patch[dr + kr][dc + kc];
                            best = fmaxf(best, s);
                        }
                    }
            }
            p1b[co * 1024 + pos] = best;
        }
    }
}

// ===========================================================================
// Kernel 2: conv2 + gates + pool, packed f32x2 (output-channel pairs).
// w2s smem layout: [copair(16)][ci*9+k (288)][2]  (even co in low word).
// ===========================================================================
#define PS_STRIDE_ROW 36
#define PS_STRIDE_CH  (34 * 36)
#define SMEM_PS_F     (32 * 34 * 36)
#define SMEM_W2_F     (32 * 32 * 9)
#define SMEM_C2_BYTES ((SMEM_PS_F + SMEM_W2_F + 64) * 4 + 1024 + 1024 + 256)

__global__ __launch_bounds__(256) void k_conv2(
    const float* __restrict__ W2, const float* __restrict__ b2)
{
    extern __shared__ float sm[];
    float* ps  = sm;
    float* w2s = sm + SMEM_PS_F;                     // 8B-aligned (39168*4 % 8 == 0)
    float* b2s = sm + SMEM_PS_F + SMEM_W2_F;
    unsigned char* m2s = (unsigned char*)(sm + SMEM_PS_F + SMEM_W2_F + 64);
    unsigned char* m3s = m2s + 1024;
    unsigned char* m4s = m3s + 1024;

    const int b = blockIdx.x, t = threadIdx.x;

    for (int i = t; i < SMEM_PS_F; i += 256) ps[i] = 0.f;
    if (t < 64) b2s[t] = b2[t];
    for (int i = t; i < 1024; i += 256) m2s[i] = g_m2[b * 1024 + i];
    __syncthreads();

    const float* p1b = g_p1 + b * 32768;
    for (int i = t; i < 32768; i += 256) {
        int ci = i >> 10, y = (i >> 5) & 31, xx = i & 31;
        ps[ci * PS_STRIDE_CH + (y + 1) * PS_STRIDE_ROW + (xx + 1)] = p1b[i];
    }
    for (int i = t; i < 1024; i += 256) {
        int r = i >> 5, c = i & 31;
        int s = 0;
        #pragma unroll
        for (int dr = 0; dr < 3; dr++) {
            int rr = r + dr;
            if (rr < 32) {
                s += m2s[rr * 32 + c];
                if (c + 1 < 32) s += m2s[rr * 32 + c + 1];
                if (c + 2 < 32) s += m2s[rr * 32 + c + 2];
            }
        }
        m3s[i] = (unsigned char)(s > 1);
    }
    __syncthreads();
    for (int i = t; i < 256; i += 256) {
        int r = i >> 4, c = i & 15;
        int s = m3s[(2 * r) * 32 + 2 * c] + m3s[(2 * r) * 32 + 2 * c + 1]
              + m3s[(2 * r + 1) * 32 + 2 * c] + m3s[(2 * r + 1) * 32 + 2 * c + 1];
        m4s[i] = (unsigned char)(s > 1);
    }
    __syncthreads();

    const int cg  = t >> 6;
    const int sp  = t & 63;
    const int pby = sp >> 3, pbx = sp & 7;
    const int r0  = 4 * pby, c0 = 4 * pbx;

    float* p2b = g_p2 + b * 16384;
    const ull* w2q = (const ull*)w2s;

    for (int half = 0; half < 2; half++) {
        __syncthreads();
        // interleave co-pairs: w2s[(copair*288 + r)*2 + (co&1)]
        for (int i = t; i < SMEM_W2_F; i += 256) {
            int co = i / 288, r = i - co * 288;
            w2s[((co >> 1) * 288 + r) * 2 + (co & 1)] = W2[half * SMEM_W2_F + i];
        }
        __syncthreads();

        #pragma unroll
        for (int tile = 0; tile < 2; tile++) {
            const int co0 = cg * 8 + tile * 4;       // local co within half
            const int qp0 = co0 >> 1;                // first co-pair index

            ull acc2[2][16];
            #pragma unroll
            for (int p = 0; p < 2; p++)
                #pragma unroll
                for (int i = 0; i < 16; i++) acc2[p][i] = 0ULL;

            for (int ci = 0; ci < 32; ci++) {
                // load 6x6 patch, duplicate-pack each value
                ull pp[6][6];
                #pragma unroll
                for (int r = 0; r < 6; r++) {
                    const float* row = ps + ci * PS_STRIDE_CH + (r0 + r) * PS_STRIDE_ROW + c0;
                    float4 v4 = *(const float4*)row;
                    float2 v2 = *(const float2*)(row + 4);
                    pp[r][0] = pk2(v4.x, v4.x); pp[r][1] = pk2(v4.y, v4.y);
                    pp[r][2] = pk2(v4.z, v4.z); pp[r][3] = pk2(v4.w, v4.w);
                    pp[r][4] = pk2(v2.x, v2.x); pp[r][5] = pk2(v2.y, v2.y);
                }
                #pragma unroll
                for (int p = 0; p < 2; p++) {
                    const int base = (qp0 + p) * 288 + ci * 9;
                    #pragma unroll
                    for (int kr = 0; kr < 3; kr++)
                        #pragma unroll
                        for (int kc = 0; kc < 3; kc++) {
                            const ull w = w2q[base + kr * 3 + kc];   // broadcast LDS.64
                            #pragma unroll
                            for (int lr = 0; lr < 4; lr++)
                                #pragma unroll
                                for (int lc = 0; lc < 4; lc++)
                                    acc2[p][lr * 4 + lc] =
                                        fma2(w, pp[lr + kr][lc + kc], acc2[p][lr * 4 + lc]);
                        }
                }
            }

            // epilogue per co-pair: unpack, gate m3 -> +bias -> relu -> pool -> gate m4
            #pragma unroll
            for (int p = 0; p < 2; p++) {
                float a0[16], a1[16];
                #pragma unroll
                for (int i = 0; i < 16; i++) upk2(acc2[p][i], a0[i], a1[i]);
                #pragma unroll
                for (int sub = 0; sub < 2; sub++) {
                    const float* a = sub ? a1 : a0;
                    const int co = half * 32 + co0 + 2 * p + sub;
                    const float bias = b2s[co];
                    #pragma unroll
                    for (int qy = 0; qy < 2; qy++)
                        #pragma unroll
                        for (int qx = 0; qx < 2; qx++) {
                            const int gy = 2 * pby + qy, gx = 2 * pbx + qx;
                            float best = 0.f;
                            if (m4s[gy * 16 + gx]) {
                                #pragma unroll
                                for (int dr = 0; dr < 2; dr++)
                                    #pragma unroll
                                    for (int dc = 0; dc < 2; dc++) {
                                        const int yy = 2 * gy + dr, xx = 2 * gx + dc;
                                        if (m3s[yy * 32 + xx]) {
                                            float v = a[(2 * qy + dr) * 4 + (2 * qx + dc)] + bias;
                                            best = fmaxf(best, v);
                                        }
                                    }
                            }
                            p2b[co * 256 + gy * 16 + gx] = best;
                        }
                }
            }
        }
    }
}

// ===========================================================================
// Kernel 3: FC1 split-K GEMM partials (unchanged).
// ===========================================================================
#define KSPLIT 64
#define FC1_SMEM_F (32 * 128 + 128 * 132)
#define FC1_SMEM_BYTES (FC1_SMEM_F * 4)

__global__ __launch_bounds__(128) void k_fc1(const float* __restrict__ Wfc1)
{
    extern __shared__ float sm[];
    float* As = sm;
    float* Bs = sm + 4096;

    const int ks = blockIdx.x, bt = blockIdx.y, t = threadIdx.x;
    const int jgrp = t & 15, bgrp = t >> 4;
    const int k0 = ks * 256;

    float acc[4][8];
    #pragma unroll
    for (int i = 0; i < 4; i++)
        #pragma unroll
        for (int j = 0; j < 8; j++) acc[i][j] = 0.f;

    for (int ch = 0; ch < 2; ch++) {
        const int kc0 = k0 + ch * 128;
        __syncthreads();
        for (int i = t; i < 4096; i += 128) {
            int bb = i >> 7, kk = i & 127;
            As[i] = g_p2[(bt * 32 + bb) * 16384 + kc0 + kk];
        }
        for (int i = t; i < 16384; i += 128) {
            int j = i >> 7, kk = i & 127;
            Bs[kk * 132 + j] = Wfc1[j * 16384 + kc0 + kk];
        }
        __syncthreads();

        #pragma unroll 4
        for (int kk = 0; kk < 128; kk++) {
            float a0 = As[(bgrp * 4 + 0) * 128 + kk];
            float a1 = As[(bgrp * 4 + 1) * 128 + kk];
            float a2 = As[(bgrp * 4 + 2) * 128 + kk];
            float a3 = As[(bgrp * 4 + 3) * 128 + kk];
            float4 v0 = *(const float4*)&Bs[kk * 132 + jgrp * 8];
            float4 v1 = *(const float4*)&Bs[kk * 132 + jgrp * 8 + 4];
            float bv[8] = {v0.x, v0.y, v0.z, v0.w, v1.x, v1.y, v1.z, v1.w};
            #pragma unroll
            for (int j = 0; j < 8; j++) {
                acc[0][j] += a0 * bv[j];
                acc[1][j] += a1 * bv[j];
                acc[2][j] += a2 * bv[j];
                acc[3][j] += a3 * bv[j];
            }
        }
    }

    #pragma unroll
    for (int i = 0; i < 4; i++) {
        const int bglob = bt * 32 + bgrp * 4 + i;
        #pragma unroll
        for (int j = 0; j < 8; j++)
            g_part[ks * (NB * 128) + bglob * 128 + jgrp * 8 + j] = acc[i][j];
    }
}

// ===========================================================================
// Kernel 4: reduce partials + bfc1 + relu + FC2.  512 threads, 4-way K split.
// ===========================================================================
__global__ __launch_bounds__(512) void k_fc2(
    const float* __restrict__ bfc1, const float* __restrict__ Wfc2,
    const float* __restrict__ bfc2, float* __restrict__ out)
{
    __shared__ float part[4][128];
    __shared__ float hs[128];
    const int b = blockIdx.x, t = threadIdx.x;
    const int j = t & 127, seg = t >> 7;

    float s = 0.f;
    #pragma unroll 16
    for (int ks = seg * 16; ks < seg * 16 + 16; ks++)
        s += g_part[ks * (NB * 128) + b * 128 + j];
    part[seg][j] = s;
    __syncthreads();

    if (t < 128) {
        float v = part[0][t] + part[1][t] + part[2][t] + part[3][t] + bfc1[t];
        hs[t] = fmaxf(v, 0.f);
    }
    __syncthreads();

    if (t < 10) {
        float a = bfc2[t];
        #pragma unroll 8
        for (int jj = 0; jj < 128; jj++) a += hs[jj] * Wfc2[t * 128 + jj];
        out[b * 10 + t] = a;
    }
}

// ===========================================================================
extern "C" void kernel_launch(void* const* d_in, const int* in_sizes, int n_in,
                              void* d_out, int out_size)
{
    const float* x    = (const float*)d_in[0];
    const int*   cmap = (const int*)  d_in[1];
    const float* W1   = (const float*)d_in[2];
    const float* b1   = (const float*)d_in[3];
    const float* W2   = (const float*)d_in[4];
    const float* b2   = (const float*)d_in[5];
    const float* Wfc1 = (const float*)d_in[6];
    const float* bfc1 = (const float*)d_in[7];
    const float* Wfc2 = (const float*)d_in[8];
    const float* bfc2 = (const float*)d_in[9];
    float* out = (float*)d_out;

    cudaFuncSetAttribute(k_conv2, cudaFuncAttributeMaxDynamicSharedMemorySize, SMEM_C2_BYTES);
    cudaFuncSetAttribute(k_fc1,   cudaFuncAttributeMaxDynamicSharedMemorySize, FC1_SMEM_BYTES);

    k_conv1<<<NB, 256>>>(x, cmap, W1, b1);
    k_conv2<<<NB, 256, SMEM_C2_BYTES>>>(W2, b2);
    dim3 g1(KSPLIT, 8);
    k_fc1<<<g1, 128, FC1_SMEM_BYTES>>>(Wfc1);
    k_fc2<<<NB, 512>>>(bfc1, Wfc2, bfc2, out);
}

// round 5
// speedup vs baseline: 1.4549x; 1.3292x over previous
#include <cuda_runtime.h>
#include <cuda_bf16.h>
#include <cstdint>

// ---------------------------------------------------------------------------
// SimpleCNN gated pipeline.  R4: conv2 via warp-level mma.sync bf16 (HMMA,
// base sm_100 ISA -- tcgen05 unavailable: harness targets sm_100 not sm_100a).
// 3-term hi/lo bf16 split for fp32-grade precision. Shifts folded into
// per-lane A-fragment addressing (no restaging).
// ---------------------------------------------------------------------------

#define NB 256

__device__ float          g_p1[NB * 32 * 32 * 32];
__device__ unsigned char  g_m2[NB * 32 * 32];
__device__ float          g_p2[NB * 64 * 16 * 16];
__device__ float          g_part[64 * NB * 128];
__device__ __nv_bfloat16  g_Bh[9 * 64 * 32];   // [shift][co][ci] hi
__device__ __nv_bfloat16  g_Bl[9 * 64 * 32];   // [shift][co][ci] lo

__device__ __forceinline__ void mma16816(float* d, const uint32_t* a, const uint32_t* b) {
    asm volatile(
        "mma.sync.aligned.m16n8k16.row.col.f32.bf16.bf16.f32 "
        "{%0,%1,%2,%3}, {%4,%5,%6,%7}, {%8,%9}, {%0,%1,%2,%3};"
        : "+f"(d[0]), "+f"(d[1]), "+f"(d[2]), "+f"(d[3])
        : "r"(a[0]), "r"(a[1]), "r"(a[2]), "r"(a[3]), "r"(b[0]), "r"(b[1]));
}

// ===========================================================================
// Kernel 0: split W2 into bf16 hi/lo, [shift][co][ci]
// ===========================================================================
__global__ void k_prep(const float* __restrict__ W2)
{
    int i = blockIdx.x * 256 + threadIdx.x;      // 72*256 = 18432 = 9*64*32
    if (i >= 9 * 64 * 32) return;
    int s = i >> 11, r = i & 2047;
    int co = r >> 5, ci = r & 31;
    float w = W2[co * 288 + ci * 9 + s];
    __nv_bfloat16 hi = __float2bfloat16(w);
    __nv_bfloat16 lo = __float2bfloat16(w - __bfloat162float(hi));
    g_Bh[(s * 64 + co) * 32 + ci] = hi;
    g_Bl[(s * 64 + co) * 32 + ci] = lo;
}

// ===========================================================================
// Kernel 1: conv1 + gates + pool (unchanged scalar)
// ===========================================================================
__global__ __launch_bounds__(256) void k_conv1(
    const float* __restrict__ x, const int* __restrict__ cmap,
    const float* __restrict__ W1, const float* __restrict__ b1)
{
    __shared__ float xs[66 * 66];
    __shared__ unsigned char cs[64 * 64];
    __shared__ unsigned char rs[64 * 64];
    __shared__ unsigned char m1s[64 * 64];
    __shared__ unsigned char m2s[32 * 32];
    __shared__ float w1s[288];
    __shared__ float b1s[32];

    const int b = blockIdx.x, t = threadIdx.x;
    const float* xb = x + b * 4096;
    const int*   cb = cmap + b * 4096;

    for (int i = t; i < 66 * 66; i += 256) {
        int r = i / 66, c = i % 66;
        float v = 0.f;
        if (r >= 1 && r <= 64 && c >= 1 && c <= 64) v = xb[(r - 1) * 64 + (c - 1)];
        xs[i] = v;
    }
    for (int i = t; i < 4096; i += 256) cs[i] = (unsigned char)cb[i];
    for (int i = t; i < 288; i += 256) w1s[i] = W1[i];
    if (t < 32)  b1s[t] = b1[t];
    __syncthreads();

    for (int i = t; i < 4096; i += 256) {
        int c = i & 63;
        int s = cs[i];
        if (c < 63) s += cs[i + 1];
        if (c < 62) s += cs[i + 2];
        rs[i] = (unsigned char)s;
    }
    __syncthreads();
    for (int i = t; i < 4096; i += 256) {
        int r = i >> 6;
        int s = rs[i];
        if (r < 63) s += rs[i + 64];
        if (r < 62) s += rs[i + 128];
        m1s[i] = (unsigned char)(s > 1);
    }
    __syncthreads();
    for (int i = t; i < 1024; i += 256) {
        int r = i >> 5, c = i & 31;
        int s = m1s[(2 * r) * 64 + 2 * c] + m1s[(2 * r) * 64 + 2 * c + 1]
              + m1s[(2 * r + 1) * 64 + 2 * c] + m1s[(2 * r + 1) * 64 + 2 * c + 1];
        m2s[i] = (unsigned char)(s > 1);
    }
    __syncthreads();
    for (int i = t; i < 1024; i += 256) g_m2[b * 1024 + i] = m2s[i];

    float* p1b = g_p1 + b * 32768;

    for (int pp = 0; pp < 4; pp++) {
        const int pos = pp * 256 + t;
        const int py = pos >> 5, px = pos & 31;
        const bool g2 = (m2s[pos] != 0);

        float patch[4][4];
        #pragma unroll
        for (int r = 0; r < 4; r++)
            #pragma unroll
            for (int c = 0; c < 4; c++)
                patch[r][c] = xs[(2 * py + r) * 66 + (2 * px + c)];

        bool mm[2][2];
        mm[0][0] = m1s[(2 * py) * 64 + 2 * px];
        mm[0][1] = m1s[(2 * py) * 64 + 2 * px + 1];
        mm[1][0] = m1s[(2 * py + 1) * 64 + 2 * px];
        mm[1][1] = m1s[(2 * py + 1) * 64 + 2 * px + 1];

        for (int co = 0; co < 32; co++) {
            float best = 0.f;
            if (g2) {
                float wv[9];
                #pragma unroll
                for (int k = 0; k < 9; k++) wv[k] = w1s[co * 9 + k];
                const float bias = b1s[co];
                #pragma unroll
                for (int dr = 0; dr < 2; dr++)
                    #pragma unroll
                    for (int dc = 0; dc < 2; dc++) {
                        if (mm[dr][dc]) {
                            float s = bias;
                            #pragma unroll
                            for (int kr = 0; kr < 3; kr++)
                                #pragma unroll
                                for (int kc = 0; kc < 3; kc++)
                                    s += wv[kr * 3 + kc] * patch[dr + kr][dc + kc];
                            best = fmaxf(best, s);
                        }
                    }
            }
            p1b[co * 1024 + pos] = best;
        }
    }
}

// ===========================================================================
// Kernel 2: conv2 via mma.sync bf16.  Grid = NB*4 (quarter batch per CTA),
// 128 threads (4 warps).  Warp tile: 64 pos (2 image rows) x 64 co.
// P smem: per-position 128B block [hi bf16 x32 | lo bf16 x32], stride 144B.
// ===========================================================================
#define C2_PSZ  (10 * 34 * 144)      // 48960
#define C2_BH   48960                // 64 co * 80B = 5120
#define C2_BL   54080                // 5120
#define C2_BIAS 59200                // 256
#define C2_M2S  59456                // 320
#define C2_M3S  59776                // 256
#define C2_M4S  60032                // 64
#define C2_SMEM 60160

__global__ __launch_bounds__(128) void k_conv2m(const float* __restrict__ b2)
{
    extern __shared__ char smc[];
    const int bq = blockIdx.x;
    const int b = bq >> 2, q = bq & 3;
    const int tx = threadIdx.x;
    const int w = tx >> 5, lane = tx & 31;
    const int g = lane >> 2, t = lane & 3;
    const int r0 = 8 * q;

    float* b2s = (float*)(smc + C2_BIAS);
    unsigned char* m2s = (unsigned char*)(smc + C2_M2S);
    unsigned char* m3s = (unsigned char*)(smc + C2_M3S);
    unsigned char* m4s = (unsigned char*)(smc + C2_M4S);

    // zero P (halo stays 0), bias, m2 slice rows r0..r0+9 (clamped -> 0)
    for (int i = tx; i < C2_PSZ / 4; i += 128) ((uint32_t*)smc)[i] = 0;
    if (tx < 64) b2s[tx] = b2[tx];
    for (int i = tx; i < 320; i += 128) {
        int r = i >> 5, c = i & 31;
        int yr = r0 + r;
        m2s[i] = (yr < 32) ? g_m2[b * 1024 + yr * 32 + c] : (unsigned char)0;
    }
    __syncthreads();

    // m3 rows r0..r0+7 (win3 of m2 > 1; bottom/right clamp)
    for (int i = tx; i < 256; i += 128) {
        int r = i >> 5, c = i & 31;
        int s = 0;
        #pragma unroll
        for (int dr = 0; dr < 3; dr++) {
            s += m2s[(r + dr) * 32 + c];
            if (c + 1 < 32) s += m2s[(r + dr) * 32 + c + 1];
            if (c + 2 < 32) s += m2s[(r + dr) * 32 + c + 2];
        }
        m3s[i] = (unsigned char)(s > 1);
    }
    // P fill: p1 rows [r0-1, r0+8] clamped -> P[y-r0+1][x+1] hi/lo blocks
    {
        const float* p1b = g_p1 + b * 32768;
        int y_lo = r0 - 1; if (y_lo < 0) y_lo = 0;
        int y_hi = r0 + 8; if (y_hi > 31) y_hi = 31;
        for (int y = y_lo; y <= y_hi; y++) {
            const float* row = p1b + y * 32;
            for (int i2 = tx; i2 < 1024; i2 += 128) {
                int ci = i2 >> 5, x = i2 & 31;
                float v = row[ci * 1024 + x];
                __nv_bfloat16 hi = __float2bfloat16(v);
                __nv_bfloat16 lo = __float2bfloat16(v - __bfloat162float(hi));
                char* blk = smc + ((y - r0 + 1) * 34 + (x + 1)) * 144;
                *(__nv_bfloat16*)(blk + 2 * ci) = hi;
                *(__nv_bfloat16*)(blk + 64 + 2 * ci) = lo;
            }
        }
    }
    __syncthreads();
    // m4 rows 4q..4q+3 (pool2 of m3 > 1), local layout [4][16]
    if (tx < 64) {
        int gyl = tx >> 4, gx = tx & 15;
        int s = m3s[(2 * gyl) * 32 + 2 * gx] + m3s[(2 * gyl) * 32 + 2 * gx + 1]
              + m3s[(2 * gyl + 1) * 32 + 2 * gx] + m3s[(2 * gyl + 1) * 32 + 2 * gx + 1];
        m4s[tx] = (unsigned char)(s > 1);
    }

    // ---- mma mainloop: 9 shifts x 2 ksteps x 3 terms x (4m x 8n) ----
    float acc[4][8][4];
    #pragma unroll
    for (int mt = 0; mt < 4; mt++)
        #pragma unroll
        for (int nt = 0; nt < 8; nt++)
            #pragma unroll
            for (int j = 0; j < 4; j++) acc[mt][nt][j] = 0.f;

    int base[4];
    #pragma unroll
    for (int mt = 0; mt < 4; mt++)
        base[mt] = (((2 * w + (mt >> 1)) * 34) + (mt & 1) * 16 + g) * 144 + t * 4;

    for (int s = 0; s < 9; s++) {
        const int sy = s / 3, sx = s - sy * 3;
        __syncthreads();                       // prior shift's B reads done
        {
            int co = tx >> 1, h2 = tx & 1;
            const uint4* sh = (const uint4*)((const char*)g_Bh + (s * 64 + co) * 64 + h2 * 32);
            uint4 v0 = sh[0], v1 = sh[1];
            uint4* dh = (uint4*)(smc + C2_BH + co * 80 + h2 * 32);
            dh[0] = v0; dh[1] = v1;
            const uint4* sl = (const uint4*)((const char*)g_Bl + (s * 64 + co) * 64 + h2 * 32);
            uint4 u0 = sl[0], u1 = sl[1];
            uint4* dl = (uint4*)(smc + C2_BL + co * 80 + h2 * 32);
            dl[0] = u0; dl[1] = u1;
        }
        __syncthreads();
        const int soff = (sy * 34 + sx) * 144;
        #pragma unroll
        for (int ks = 0; ks < 2; ks++) {
            uint32_t Ah[4][4], Al[4][4];
            #pragma unroll
            for (int mt = 0; mt < 4; mt++) {
                const char* pa = smc + base[mt] + soff + ks * 32;
                Ah[mt][0] = *(const uint32_t*)(pa);
                Ah[mt][1] = *(const uint32_t*)(pa + 8 * 144);
                Ah[mt][2] = *(const uint32_t*)(pa + 16);
                Ah[mt][3] = *(const uint32_t*)(pa + 8 * 144 + 16);
                Al[mt][0] = *(const uint32_t*)(pa + 64);
                Al[mt][1] = *(const uint32_t*)(pa + 64 + 8 * 144);
                Al[mt][2] = *(const uint32_t*)(pa + 64 + 16);
                Al[mt][3] = *(const uint32_t*)(pa + 64 + 8 * 144 + 16);
            }
            #pragma unroll
            for (int term = 0; term < 3; term++) {
                const char* bb = smc + (term == 1 ? C2_BL : C2_BH) + g * 80 + ks * 32 + t * 4;
                uint32_t Bf[8][2];
                #pragma unroll
                for (int nt = 0; nt < 8; nt++) {
                    Bf[nt][0] = *(const uint32_t*)(bb + nt * 640);
                    Bf[nt][1] = *(const uint32_t*)(bb + nt * 640 + 16);
                }
                #pragma unroll
                for (int mt = 0; mt < 4; mt++) {
                    const uint32_t* A = (term == 2) ? Al[mt] : Ah[mt];
                    #pragma unroll
                    for (int nt = 0; nt < 8; nt++)
                        mma16816(acc[mt][nt], A, Bf[nt]);
                }
            }
        }
    }

    // ---- epilogue: m3 gate + bias + relu -> pool (vert in-reg, horiz shfl)
    //      -> m4 gate -> store.  Warp owns pooled row gy = 4q + w.
    const int gy = 4 * q + w;
    float* dst = g_p2 + b * 16384 + gy * 16;
    #pragma unroll
    for (int mh = 0; mh < 2; mh++) {            // x-half (mt&1)
        #pragma unroll
        for (int nt = 0; nt < 8; nt++) {
            const float bias0 = b2s[nt * 8 + 2 * t];
            const float bias1 = b2s[nt * 8 + 2 * t + 1];
            float v0[2], v1[2], v2[2], v3[2];
            #pragma unroll
            for (int mp = 0; mp < 2; mp++) {    // y0 + mp
                const int mt = mh + 2 * mp;
                const int mrow = (2 * w + mp) * 32 + mh * 16 + g;
                const bool g3a = m3s[mrow] != 0;
                const bool g3b = m3s[mrow + 8] != 0;
                v0[mp] = g3a ? fmaxf(acc[mt][nt][0] + bias0, 0.f) : 0.f;
                v1[mp] = g3a ? fmaxf(acc[mt][nt][1] + bias1, 0.f) : 0.f;
                v2[mp] = g3b ? fmaxf(acc[mt][nt][2] + bias0, 0.f) : 0.f;
                v3[mp] = g3b ? fmaxf(acc[mt][nt][3] + bias1, 0.f) : 0.f;
            }
            float o0 = fmaxf(v0[0], v0[1]);
            float o1 = fmaxf(v1[0], v1[1]);
            float o2 = fmaxf(v2[0], v2[1]);
            float o3 = fmaxf(v3[0], v3[1]);
            o0 = fmaxf(o0, __shfl_xor_sync(0xffffffffu, o0, 4));
            o1 = fmaxf(o1, __shfl_xor_sync(0xffffffffu, o1, 4));
            o2 = fmaxf(o2, __shfl_xor_sync(0xffffffffu, o2, 4));
            o3 = fmaxf(o3, __shfl_xor_sync(0xffffffffu, o3, 4));
            if ((lane & 4) == 0) {
                const int gxa = mh * 8 + (g >> 1);
                const int gxb = gxa + 4;
                const bool g4a = m4s[w * 16 + gxa] != 0;
                const bool g4b = m4s[w * 16 + gxb] != 0;
                const int co = nt * 8 + 2 * t;
                dst[co * 256 + gxa]       = g4a ? o0 : 0.f;
                dst[(co + 1) * 256 + gxa] = g4a ? o1 : 0.f;
                dst[co * 256 + gxb]       = g4b ? o2 : 0.f;
                dst[(co + 1) * 256 + gxb] = g4b ? o3 : 0.f;
            }
        }
    }
}

// ===========================================================================
// Kernel 3: FC1 split-K GEMM partials (unchanged)
// ===========================================================================
#define KSPLIT 64
#define FC1_SMEM_F (32 * 128 + 128 * 132)
#define FC1_SMEM_BYTES (FC1_SMEM_F * 4)

__global__ __launch_bounds__(128) void k_fc1(const float* __restrict__ Wfc1)
{
    extern __shared__ float sm[];
    float* As = sm;
    float* Bs = sm + 4096;

    const int ks = blockIdx.x, bt = blockIdx.y, t = threadIdx.x;
    const int jgrp = t & 15, bgrp = t >> 4;
    const int k0 = ks * 256;

    float acc[4][8];
    #pragma unroll
    for (int i = 0; i < 4; i++)
        #pragma unroll
        for (int j = 0; j < 8; j++) acc[i][j] = 0.f;

    for (int ch = 0; ch < 2; ch++) {
        const int kc0 = k0 + ch * 128;
        __syncthreads();
        for (int i = t; i < 4096; i += 128) {
            int bb = i >> 7, kk = i & 127;
            As[i] = g_p2[(bt * 32 + bb) * 16384 + kc0 + kk];
        }
        for (int i = t; i < 16384; i += 128) {
            int j = i >> 7, kk = i & 127;
            Bs[kk * 132 + j] = Wfc1[j * 16384 + kc0 + kk];
        }
        __syncthreads();

        #pragma unroll 4
        for (int kk = 0; kk < 128; kk++) {
            float a0 = As[(bgrp * 4 + 0) * 128 + kk];
            float a1 = As[(bgrp * 4 + 1) * 128 + kk];
            float a2 = As[(bgrp * 4 + 2) * 128 + kk];
            float a3 = As[(bgrp * 4 + 3) * 128 + kk];
            float4 q0 = *(const float4*)&Bs[kk * 132 + jgrp * 8];
            float4 q1 = *(const float4*)&Bs[kk * 132 + jgrp * 8 + 4];
            float bv[8] = {q0.x, q0.y, q0.z, q0.w, q1.x, q1.y, q1.z, q1.w};
            #pragma unroll
            for (int j = 0; j < 8; j++) {
                acc[0][j] += a0 * bv[j];
                acc[1][j] += a1 * bv[j];
                acc[2][j] += a2 * bv[j];
                acc[3][j] += a3 * bv[j];
            }
        }
    }

    #pragma unroll
    for (int i = 0; i < 4; i++) {
        const int bglob = bt * 32 + bgrp * 4 + i;
        #pragma unroll
        for (int j = 0; j < 8; j++)
            g_part[ks * (NB * 128) + bglob * 128 + jgrp * 8 + j] = acc[i][j];
    }
}

// ===========================================================================
// Kernel 4: reduce partials + bfc1 + relu + FC2 (512 threads)
// ===========================================================================
__global__ __launch_bounds__(512) void k_fc2(
    const float* __restrict__ bfc1, const float* __restrict__ Wfc2,
    const float* __restrict__ bfc2, float* __restrict__ out)
{
    __shared__ float part[4][128];
    __shared__ float hs[128];
    const int b = blockIdx.x, t = threadIdx.x;
    const int j = t & 127, seg = t >> 7;

    float s = 0.f;
    #pragma unroll 16
    for (int ks = seg * 16; ks < seg * 16 + 16; ks++)
        s += g_part[ks * (NB * 128) + b * 128 + j];
    part[seg][j] = s;
    __syncthreads();

    if (t < 128) {
        float v = part[0][t] + part[1][t] + part[2][t] + part[3][t] + bfc1[t];
        hs[t] = fmaxf(v, 0.f);
    }
    __syncthreads();

    if (t < 10) {
        float a = bfc2[t];
        #pragma unroll 8
        for (int jj = 0; jj < 128; jj++) a += hs[jj] * Wfc2[t * 128 + jj];
        out[b * 10 + t] = a;
    }
}

// ===========================================================================
extern "C" void kernel_launch(void* const* d_in, const int* in_sizes, int n_in,
                              void* d_out, int out_size)
{
    const float* x    = (const float*)d_in[0];
    const int*   cmap = (const int*)  d_in[1];
    const float* W1   = (const float*)d_in[2];
    const float* b1   = (const float*)d_in[3];
    const float* W2   = (const float*)d_in[4];
    const float* b2   = (const float*)d_in[5];
    const float* Wfc1 = (const float*)d_in[6];
    const float* bfc1 = (const float*)d_in[7];
    const float* Wfc2 = (const float*)d_in[8];
    const float* bfc2 = (const float*)d_in[9];
    float* out = (float*)d_out;

    cudaFuncSetAttribute(k_conv2m, cudaFuncAttributeMaxDynamicSharedMemorySize, C2_SMEM);
    cudaFuncSetAttribute(k_fc1,    cudaFuncAttributeMaxDynamicSharedMemorySize, FC1_SMEM_BYTES);

    k_prep<<<72, 256>>>(W2);
    k_conv1<<<NB, 256>>>(x, cmap, W1, b1);
    k_conv2m<<<NB * 4, 128, C2_SMEM>>>(b2);
    dim3 g1(KSPLIT, 8);
    k_fc1<<<g1, 128, FC1_SMEM_BYTES>>>(Wfc1);
    k_fc2<<<NB, 512>>>(bfc1, Wfc2, bfc2, out);
}

// round 6
// speedup vs baseline: 1.8368x; 1.2625x over previous
#include <cuda_runtime.h>
#include <cuda_bf16.h>
#include <cstdint>

// ---------------------------------------------------------------------------
// SimpleCNN gated pipeline.  R5: FC1 moved to mma.sync bf16 (3-term hi/lo)
// with global-direct fragments; conv2 epilogue emits p2 as bf16 hi/lo.
// ---------------------------------------------------------------------------

#define NB 256

__device__ float          g_p1[NB * 32 * 32 * 32];
__device__ unsigned char  g_m2[NB * 32 * 32];
__device__ __nv_bfloat16  g_p2h[NB * 16384];
__device__ __nv_bfloat16  g_p2l[NB * 16384];
__device__ __nv_bfloat16  g_Bh[9 * 64 * 32];     // conv2 weights hi [shift][co][ci]
__device__ __nv_bfloat16  g_Bl[9 * 64 * 32];
__device__ __nv_bfloat16  g_Wh[128 * 16384];     // fc1 weights hi [j][k]
__device__ __nv_bfloat16  g_Wl[128 * 16384];
#define KSPLIT 128
__device__ float          g_part[KSPLIT * 256 * 128];   // 16.8MB

__device__ __forceinline__ void mma16816(float* d, const uint32_t* a, const uint32_t* b) {
    asm volatile(
        "mma.sync.aligned.m16n8k16.row.col.f32.bf16.bf16.f32 "
        "{%0,%1,%2,%3}, {%4,%5,%6,%7}, {%8,%9}, {%0,%1,%2,%3};"
        : "+f"(d[0]), "+f"(d[1]), "+f"(d[2]), "+f"(d[3])
        : "r"(a[0]), "r"(a[1]), "r"(a[2]), "r"(a[3]), "r"(b[0]), "r"(b[1]));
}

// ===========================================================================
// Kernel 0a: split W2 into bf16 hi/lo, [shift][co][ci]
// ===========================================================================
__global__ void k_prep(const float* __restrict__ W2)
{
    int i = blockIdx.x * 256 + threadIdx.x;      // 72*256 = 18432 = 9*64*32
    if (i >= 9 * 64 * 32) return;
    int s = i >> 11, r = i & 2047;
    int co = r >> 5, ci = r & 31;
    float w = W2[co * 288 + ci * 9 + s];
    __nv_bfloat16 hi = __float2bfloat16(w);
    __nv_bfloat16 lo = __float2bfloat16(w - __bfloat162float(hi));
    g_Bh[(s * 64 + co) * 32 + ci] = hi;
    g_Bl[(s * 64 + co) * 32 + ci] = lo;
}

// ===========================================================================
// Kernel 0b: split Wfc1 into bf16 hi/lo
// ===========================================================================
__global__ void k_prep_fc1(const float* __restrict__ Wfc1)
{
    int i = blockIdx.x * 256 + threadIdx.x;      // 8192 blocks
    float w = Wfc1[i];
    __nv_bfloat16 hi = __float2bfloat16(w);
    __nv_bfloat16 lo = __float2bfloat16(w - __bfloat162float(hi));
    g_Wh[i] = hi;
    g_Wl[i] = lo;
}

// ===========================================================================
// Kernel 1: conv1 + gates + pool (unchanged scalar)
// ===========================================================================
__global__ __launch_bounds__(256) void k_conv1(
    const float* __restrict__ x, const int* __restrict__ cmap,
    const float* __restrict__ W1, const float* __restrict__ b1)
{
    __shared__ float xs[66 * 66];
    __shared__ unsigned char cs[64 * 64];
    __shared__ unsigned char rs[64 * 64];
    __shared__ unsigned char m1s[64 * 64];
    __shared__ unsigned char m2s[32 * 32];
    __shared__ float w1s[288];
    __shared__ float b1s[32];

    const int b = blockIdx.x, t = threadIdx.x;
    const float* xb = x + b * 4096;
    const int*   cb = cmap + b * 4096;

    for (int i = t; i < 66 * 66; i += 256) {
        int r = i / 66, c = i % 66;
        float v = 0.f;
        if (r >= 1 && r <= 64 && c >= 1 && c <= 64) v = xb[(r - 1) * 64 + (c - 1)];
        xs[i] = v;
    }
    for (int i = t; i < 4096; i += 256) cs[i] = (unsigned char)cb[i];
    for (int i = t; i < 288; i += 256) w1s[i] = W1[i];
    if (t < 32)  b1s[t] = b1[t];
    __syncthreads();

    for (int i = t; i < 4096; i += 256) {
        int c = i & 63;
        int s = cs[i];
        if (c < 63) s += cs[i + 1];
        if (c < 62) s += cs[i + 2];
        rs[i] = (unsigned char)s;
    }
    __syncthreads();
    for (int i = t; i < 4096; i += 256) {
        int r = i >> 6;
        int s = rs[i];
        if (r < 63) s += rs[i + 64];
        if (r < 62) s += rs[i + 128];
        m1s[i] = (unsigned char)(s > 1);
    }
    __syncthreads();
    for (int i = t; i < 1024; i += 256) {
        int r = i >> 5, c = i & 31;
        int s = m1s[(2 * r) * 64 + 2 * c] + m1s[(2 * r) * 64 + 2 * c + 1]
              + m1s[(2 * r + 1) * 64 + 2 * c] + m1s[(2 * r + 1) * 64 + 2 * c + 1];
        m2s[i] = (unsigned char)(s > 1);
    }
    __syncthreads();
    for (int i = t; i < 1024; i += 256) g_m2[b * 1024 + i] = m2s[i];

    float* p1b = g_p1 + b * 32768;

    for (int pp = 0; pp < 4; pp++) {
        const int pos = pp * 256 + t;
        const int py = pos >> 5, px = pos & 31;
        const bool g2 = (m2s[pos] != 0);

        float patch[4][4];
        #pragma unroll
        for (int r = 0; r < 4; r++)
            #pragma unroll
            for (int c = 0; c < 4; c++)
                patch[r][c] = xs[(2 * py + r) * 66 + (2 * px + c)];

        bool mm[2][2];
        mm[0][0] = m1s[(2 * py) * 64 + 2 * px];
        mm[0][1] = m1s[(2 * py) * 64 + 2 * px + 1];
        mm[1][0] = m1s[(2 * py + 1) * 64 + 2 * px];
        mm[1][1] = m1s[(2 * py + 1) * 64 + 2 * px + 1];

        for (int co = 0; co < 32; co++) {
            float best = 0.f;
            if (g2) {
                float wv[9];
                #pragma unroll
                for (int k = 0; k < 9; k++) wv[k] = w1s[co * 9 + k];
                const float bias = b1s[co];
                #pragma unroll
                for (int dr = 0; dr < 2; dr++)
                    #pragma unroll
                    for (int dc = 0; dc < 2; dc++) {
                        if (mm[dr][dc]) {
                            float s = bias;
                            #pragma unroll
                            for (int kr = 0; kr < 3; kr++)
                                #pragma unroll
                                for (int kc = 0; kc < 3; kc++)
                                    s += wv[kr * 3 + kc] * patch[dr + kr][dc + kc];
                            best = fmaxf(best, s);
                        }
                    }
            }
            p1b[co * 1024 + pos] = best;
        }
    }
}

// ===========================================================================
// Kernel 2: conv2 via mma.sync bf16.  Grid = NB*4, 128 threads (4 warps).
// Epilogue stores p2 as bf16 hi/lo for fc1.
// ===========================================================================
#define C2_PSZ  (10 * 34 * 144)      // 48960
#define C2_BH   48960
#define C2_BL   54080
#define C2_BIAS 59200
#define C2_M2S  59456
#define C2_M3S  59776
#define C2_M4S  60032
#define C2_SMEM 60160

__device__ __forceinline__ void store_p2(int idx, float v) {
    __nv_bfloat16 hi = __float2bfloat16(v);
    __nv_bfloat16 lo = __float2bfloat16(v - __bfloat162float(hi));
    g_p2h[idx] = hi;
    g_p2l[idx] = lo;
}

__global__ __launch_bounds__(128) void k_conv2m(const float* __restrict__ b2)
{
    extern __shared__ char smc[];
    const int bq = blockIdx.x;
    const int b = bq >> 2, q = bq & 3;
    const int tx = threadIdx.x;
    const int w = tx >> 5, lane = tx & 31;
    const int g = lane >> 2, t = lane & 3;
    const int r0 = 8 * q;

    float* b2s = (float*)(smc + C2_BIAS);
    unsigned char* m2s = (unsigned char*)(smc + C2_M2S);
    unsigned char* m3s = (unsigned char*)(smc + C2_M3S);
    unsigned char* m4s = (unsigned char*)(smc + C2_M4S);

    for (int i = tx; i < C2_PSZ / 4; i += 128) ((uint32_t*)smc)[i] = 0;
    if (tx < 64) b2s[tx] = b2[tx];
    for (int i = tx; i < 320; i += 128) {
        int r = i >> 5, c = i & 31;
        int yr = r0 + r;
        m2s[i] = (yr < 32) ? g_m2[b * 1024 + yr * 32 + c] : (unsigned char)0;
    }
    __syncthreads();

    for (int i = tx; i < 256; i += 128) {
        int r = i >> 5, c = i & 31;
        int s = 0;
        #pragma unroll
        for (int dr = 0; dr < 3; dr++) {
            s += m2s[(r + dr) * 32 + c];
            if (c + 1 < 32) s += m2s[(r + dr) * 32 + c + 1];
            if (c + 2 < 32) s += m2s[(r + dr) * 32 + c + 2];
        }
        m3s[i] = (unsigned char)(s > 1);
    }
    {
        const float* p1b = g_p1 + b * 32768;
        int y_lo = r0 - 1; if (y_lo < 0) y_lo = 0;
        int y_hi = r0 + 8; if (y_hi > 31) y_hi = 31;
        for (int y = y_lo; y <= y_hi; y++) {
            const float* row = p1b + y * 32;
            for (int i2 = tx; i2 < 1024; i2 += 128) {
                int ci = i2 >> 5, x = i2 & 31;
                float v = row[ci * 1024 + x];
                __nv_bfloat16 hi = __float2bfloat16(v);
                __nv_bfloat16 lo = __float2bfloat16(v - __bfloat162float(hi));
                char* blk = smc + ((y - r0 + 1) * 34 + (x + 1)) * 144;
                *(__nv_bfloat16*)(blk + 2 * ci) = hi;
                *(__nv_bfloat16*)(blk + 64 + 2 * ci) = lo;
            }
        }
    }
    __syncthreads();
    if (tx < 64) {
        int gyl = tx >> 4, gx = tx & 15;
        int s = m3s[(2 * gyl) * 32 + 2 * gx] + m3s[(2 * gyl) * 32 + 2 * gx + 1]
              + m3s[(2 * gyl + 1) * 32 + 2 * gx] + m3s[(2 * gyl + 1) * 32 + 2 * gx + 1];
        m4s[tx] = (unsigned char)(s > 1);
    }

    float acc[4][8][4];
    #pragma unroll
    for (int mt = 0; mt < 4; mt++)
        #pragma unroll
        for (int nt = 0; nt < 8; nt++)
            #pragma unroll
            for (int j = 0; j < 4; j++) acc[mt][nt][j] = 0.f;

    int base[4];
    #pragma unroll
    for (int mt = 0; mt < 4; mt++)
        base[mt] = (((2 * w + (mt >> 1)) * 34) + (mt & 1) * 16 + g) * 144 + t * 4;

    for (int s = 0; s < 9; s++) {
        const int sy = s / 3, sx = s - sy * 3;
        __syncthreads();
        {
            int co = tx >> 1, h2 = tx & 1;
            const uint4* sh = (const uint4*)((const char*)g_Bh + (s * 64 + co) * 64 + h2 * 32);
            uint4 v0 = sh[0], v1 = sh[1];
            uint4* dh = (uint4*)(smc + C2_BH + co * 80 + h2 * 32);
            dh[0] = v0; dh[1] = v1;
            const uint4* sl = (const uint4*)((const char*)g_Bl + (s * 64 + co) * 64 + h2 * 32);
            uint4 u0 = sl[0], u1 = sl[1];
            uint4* dl = (uint4*)(smc + C2_BL + co * 80 + h2 * 32);
            dl[0] = u0; dl[1] = u1;
        }
        __syncthreads();
        const int soff = (sy * 34 + sx) * 144;
        #pragma unroll
        for (int ks = 0; ks < 2; ks++) {
            uint32_t Ah[4][4], Al[4][4];
            #pragma unroll
            for (int mt = 0; mt < 4; mt++) {
                const char* pa = smc + base[mt] + soff + ks * 32;
                Ah[mt][0] = *(const uint32_t*)(pa);
                Ah[mt][1] = *(const uint32_t*)(pa + 8 * 144);
                Ah[mt][2] = *(const uint32_t*)(pa + 16);
                Ah[mt][3] = *(const uint32_t*)(pa + 8 * 144 + 16);
                Al[mt][0] = *(const uint32_t*)(pa + 64);
                Al[mt][1] = *(const uint32_t*)(pa + 64 + 8 * 144);
                Al[mt][2] = *(const uint32_t*)(pa + 64 + 16);
                Al[mt][3] = *(const uint32_t*)(pa + 64 + 8 * 144 + 16);
            }
            #pragma unroll
            for (int term = 0; term < 3; term++) {
                const char* bb = smc + (term == 1 ? C2_BL : C2_BH) + g * 80 + ks * 32 + t * 4;
                uint32_t Bf[8][2];
                #pragma unroll
                for (int nt = 0; nt < 8; nt++) {
                    Bf[nt][0] = *(const uint32_t*)(bb + nt * 640);
                    Bf[nt][1] = *(const uint32_t*)(bb + nt * 640 + 16);
                }
                #pragma unroll
                for (int mt = 0; mt < 4; mt++) {
                    const uint32_t* A = (term == 2) ? Al[mt] : Ah[mt];
                    #pragma unroll
                    for (int nt = 0; nt < 8; nt++)
                        mma16816(acc[mt][nt], A, Bf[nt]);
                }
            }
        }
    }

    const int gy = 4 * q + w;
    const int dbase = b * 16384 + gy * 16;
    #pragma unroll
    for (int mh = 0; mh < 2; mh++) {
        #pragma unroll
        for (int nt = 0; nt < 8; nt++) {
            const float bias0 = b2s[nt * 8 + 2 * t];
            const float bias1 = b2s[nt * 8 + 2 * t + 1];
            float v0[2], v1[2], v2[2], v3[2];
            #pragma unroll
            for (int mp = 0; mp < 2; mp++) {
                const int mt = mh + 2 * mp;
                const int mrow = (2 * w + mp) * 32 + mh * 16 + g;
                const bool g3a = m3s[mrow] != 0;
                const bool g3b = m3s[mrow + 8] != 0;
                v0[mp] = g3a ? fmaxf(acc[mt][nt][0] + bias0, 0.f) : 0.f;
                v1[mp] = g3a ? fmaxf(acc[mt][nt][1] + bias1, 0.f) : 0.f;
                v2[mp] = g3b ? fmaxf(acc[mt][nt][2] + bias0, 0.f) : 0.f;
                v3[mp] = g3b ? fmaxf(acc[mt][nt][3] + bias1, 0.f) : 0.f;
            }
            float o0 = fmaxf(v0[0], v0[1]);
            float o1 = fmaxf(v1[0], v1[1]);
            float o2 = fmaxf(v2[0], v2[1]);
            float o3 = fmaxf(v3[0], v3[1]);
            o0 = fmaxf(o0, __shfl_xor_sync(0xffffffffu, o0, 4));
            o1 = fmaxf(o1, __shfl_xor_sync(0xffffffffu, o1, 4));
            o2 = fmaxf(o2, __shfl_xor_sync(0xffffffffu, o2, 4));
            o3 = fmaxf(o3, __shfl_xor_sync(0xffffffffu, o3, 4));
            if ((lane & 4) == 0) {
                const int gxa = mh * 8 + (g >> 1);
                const int gxb = gxa + 4;
                const bool g4a = m4s[w * 16 + gxa] != 0;
                const bool g4b = m4s[w * 16 + gxb] != 0;
                const int co = nt * 8 + 2 * t;
                store_p2(dbase + co * 256 + gxa,       g4a ? o0 : 0.f);
                store_p2(dbase + (co + 1) * 256 + gxa, g4a ? o1 : 0.f);
                store_p2(dbase + co * 256 + gxb,       g4b ? o2 : 0.f);
                store_p2(dbase + (co + 1) * 256 + gxb, g4b ? o3 : 0.f);
            }
        }
    }
}

// ===========================================================================
// Kernel 3: FC1 via mma.sync bf16 (3-term hi/lo), global-direct fragments.
// Grid = KSPLIT(128), 256 threads (8 warps: 4m x 2n), warp tile 64x64.
// Partials -> g_part[ks][b(256)][j(128)].
// ===========================================================================
__global__ __launch_bounds__(256) void k_fc1m()
{
    const int ks = blockIdx.x;
    const int tx = threadIdx.x;
    const int warp = tx >> 5, lane = tx & 31;
    const int g = lane >> 2, t = lane & 3;
    const int wm = warp >> 1, wn = warp & 1;
    const int row0 = wm * 64, col0 = wn * 64;
    const int k0 = ks * 128;

    float acc[4][8][4];
    #pragma unroll
    for (int mt = 0; mt < 4; mt++)
        #pragma unroll
        for (int nt = 0; nt < 8; nt++)
            #pragma unroll
            for (int j = 0; j < 4; j++) acc[mt][nt][j] = 0.f;

    #pragma unroll 2
    for (int kk = 0; kk < 8; kk++) {
        const int kb = k0 + kk * 16;
        uint32_t Ah[4][4], Al[4][4];
        #pragma unroll
        for (int mt = 0; mt < 4; mt++) {
            const int r = row0 + mt * 16 + g;
            const __nv_bfloat16* ph = g_p2h + r * 16384 + kb + 2 * t;
            const __nv_bfloat16* pl = g_p2l + r * 16384 + kb + 2 * t;
            Ah[mt][0] = *(const uint32_t*)(ph);
            Ah[mt][1] = *(const uint32_t*)(ph + 8 * 16384);
            Ah[mt][2] = *(const uint32_t*)(ph + 8);
            Ah[mt][3] = *(const uint32_t*)(ph + 8 * 16384 + 8);
            Al[mt][0] = *(const uint32_t*)(pl);
            Al[mt][1] = *(const uint32_t*)(pl + 8 * 16384);
            Al[mt][2] = *(const uint32_t*)(pl + 8);
            Al[mt][3] = *(const uint32_t*)(pl + 8 * 16384 + 8);
        }
        #pragma unroll
        for (int term = 0; term < 3; term++) {
            const __nv_bfloat16* wbase = (term == 1) ? g_Wl : g_Wh;
            uint32_t Bf[8][2];
            #pragma unroll
            for (int nt = 0; nt < 8; nt++) {
                const int j = col0 + nt * 8 + g;
                const __nv_bfloat16* pb = wbase + j * 16384 + kb + 2 * t;
                Bf[nt][0] = *(const uint32_t*)(pb);
                Bf[nt][1] = *(const uint32_t*)(pb + 8);
            }
            #pragma unroll
            for (int mt = 0; mt < 4; mt++) {
                const uint32_t* A = (term == 2) ? Al[mt] : Ah[mt];
                #pragma unroll
                for (int nt = 0; nt < 8; nt++)
                    mma16816(acc[mt][nt], A, Bf[nt]);
            }
        }
    }

    float* dst = g_part + ks * 32768;
    #pragma unroll
    for (int mt = 0; mt < 4; mt++) {
        const int r = row0 + mt * 16 + g;
        #pragma unroll
        for (int nt = 0; nt < 8; nt++) {
            const int c = col0 + nt * 8 + 2 * t;
            *(float2*)(dst + r * 128 + c)       = make_float2(acc[mt][nt][0], acc[mt][nt][1]);
            *(float2*)(dst + (r + 8) * 128 + c) = make_float2(acc[mt][nt][2], acc[mt][nt][3]);
        }
    }
}

// ===========================================================================
// Kernel 4: reduce 128 partials + bfc1 + relu + FC2 (512 threads)
// ===========================================================================
__global__ __launch_bounds__(512) void k_fc2(
    const float* __restrict__ bfc1, const float* __restrict__ Wfc2,
    const float* __restrict__ bfc2, float* __restrict__ out)
{
    __shared__ float part[4][128];
    __shared__ float hs[128];
    const int b = blockIdx.x, t = threadIdx.x;
    const int j = t & 127, seg = t >> 7;

    float s = 0.f;
    #pragma unroll 8
    for (int ks = seg * 32; ks < seg * 32 + 32; ks++)
        s += g_part[ks * 32768 + b * 128 + j];
    part[seg][j] = s;
    __syncthreads();

    if (t < 128) {
        float v = part[0][t] + part[1][t] + part[2][t] + part[3][t] + bfc1[t];
        hs[t] = fmaxf(v, 0.f);
    }
    __syncthreads();

    if (t < 10) {
        float a = bfc2[t];
        #pragma unroll 8
        for (int jj = 0; jj < 128; jj++) a += hs[jj] * Wfc2[t * 128 + jj];
        out[b * 10 + t] = a;
    }
}

// ===========================================================================
extern "C" void kernel_launch(void* const* d_in, const int* in_sizes, int n_in,
                              void* d_out, int out_size)
{
    const float* x    = (const float*)d_in[0];
    const int*   cmap = (const int*)  d_in[1];
    const float* W1   = (const float*)d_in[2];
    const float* b1   = (const float*)d_in[3];
    const float* W2   = (const float*)d_in[4];
    const float* b2   = (const float*)d_in[5];
    const float* Wfc1 = (const float*)d_in[6];
    const float* bfc1 = (const float*)d_in[7];
    const float* Wfc2 = (const float*)d_in[8];
    const float* bfc2 = (const float*)d_in[9];
    float* out = (float*)d_out;

    cudaFuncSetAttribute(k_conv2m, cudaFuncAttributeMaxDynamicSharedMemorySize, C2_SMEM);

    k_prep<<<72, 256>>>(W2);
    k_prep_fc1<<<8192, 256>>>(Wfc1);
    k_conv1<<<NB, 256>>>(x, cmap, W1, b1);
    k_conv2m<<<NB * 4, 128, C2_SMEM>>>(b2);
    k_fc1m<<<KSPLIT, 256>>>();
    k_fc2<<<NB, 512>>>(bfc1, Wfc2, bfc2, out);
}

// round 7
// speedup vs baseline: 2.0108x; 1.0947x over previous
#include <cuda_runtime.h>
#include <cuda_bf16.h>
#include <cstdint>

// ---------------------------------------------------------------------------
// SimpleCNN gated pipeline.  R6: conv2m re-tiled for occupancy: warp tile
// 64pos x 32co, 4 CTAs/SM (launch_bounds(128,4)), A-register reuse via
// term ordering (ah*bh, ah*bl, al*bh).
// ---------------------------------------------------------------------------

#define NB 256

__device__ float          g_p1[NB * 32 * 32 * 32];
__device__ unsigned char  g_m2[NB * 32 * 32];
__device__ __nv_bfloat16  g_p2h[NB * 16384];
__device__ __nv_bfloat16  g_p2l[NB * 16384];
__device__ __nv_bfloat16  g_Bh[9 * 64 * 32];     // conv2 weights hi [shift][co][ci]
__device__ __nv_bfloat16  g_Bl[9 * 64 * 32];
__device__ __nv_bfloat16  g_Wh[128 * 16384];     // fc1 weights hi [j][k]
__device__ __nv_bfloat16  g_Wl[128 * 16384];
#define KSPLIT 128
__device__ float          g_part[KSPLIT * 256 * 128];   // 16.8MB

__device__ __forceinline__ void mma16816(float* d, const uint32_t* a, const uint32_t* b) {
    asm volatile(
        "mma.sync.aligned.m16n8k16.row.col.f32.bf16.bf16.f32 "
        "{%0,%1,%2,%3}, {%4,%5,%6,%7}, {%8,%9}, {%0,%1,%2,%3};"
        : "+f"(d[0]), "+f"(d[1]), "+f"(d[2]), "+f"(d[3])
        : "r"(a[0]), "r"(a[1]), "r"(a[2]), "r"(a[3]), "r"(b[0]), "r"(b[1]));
}

// ===========================================================================
// Kernel 0a: split W2 into bf16 hi/lo, [shift][co][ci]
// ===========================================================================
__global__ void k_prep(const float* __restrict__ W2)
{
    int i = blockIdx.x * 256 + threadIdx.x;
    if (i >= 9 * 64 * 32) return;
    int s = i >> 11, r = i & 2047;
    int co = r >> 5, ci = r & 31;
    float w = W2[co * 288 + ci * 9 + s];
    __nv_bfloat16 hi = __float2bfloat16(w);
    __nv_bfloat16 lo = __float2bfloat16(w - __bfloat162float(hi));
    g_Bh[(s * 64 + co) * 32 + ci] = hi;
    g_Bl[(s * 64 + co) * 32 + ci] = lo;
}

// ===========================================================================
// Kernel 0b: split Wfc1 into bf16 hi/lo
// ===========================================================================
__global__ void k_prep_fc1(const float* __restrict__ Wfc1)
{
    int i = blockIdx.x * 256 + threadIdx.x;
    float w = Wfc1[i];
    __nv_bfloat16 hi = __float2bfloat16(w);
    __nv_bfloat16 lo = __float2bfloat16(w - __bfloat162float(hi));
    g_Wh[i] = hi;
    g_Wl[i] = lo;
}

// ===========================================================================
// Kernel 1: conv1 + gates + pool (unchanged scalar)
// ===========================================================================
__global__ __launch_bounds__(256) void k_conv1(
    const float* __restrict__ x, const int* __restrict__ cmap,
    const float* __restrict__ W1, const float* __restrict__ b1)
{
    __shared__ float xs[66 * 66];
    __shared__ unsigned char cs[64 * 64];
    __shared__ unsigned char rs[64 * 64];
    __shared__ unsigned char m1s[64 * 64];
    __shared__ unsigned char m2s[32 * 32];
    __shared__ float w1s[288];
    __shared__ float b1s[32];

    const int b = blockIdx.x, t = threadIdx.x;
    const float* xb = x + b * 4096;
    const int*   cb = cmap + b * 4096;

    for (int i = t; i < 66 * 66; i += 256) {
        int r = i / 66, c = i % 66;
        float v = 0.f;
        if (r >= 1 && r <= 64 && c >= 1 && c <= 64) v = xb[(r - 1) * 64 + (c - 1)];
        xs[i] = v;
    }
    for (int i = t; i < 4096; i += 256) cs[i] = (unsigned char)cb[i];
    for (int i = t; i < 288; i += 256) w1s[i] = W1[i];
    if (t < 32)  b1s[t] = b1[t];
    __syncthreads();

    for (int i = t; i < 4096; i += 256) {
        int c = i & 63;
        int s = cs[i];
        if (c < 63) s += cs[i + 1];
        if (c < 62) s += cs[i + 2];
        rs[i] = (unsigned char)s;
    }
    __syncthreads();
    for (int i = t; i < 4096; i += 256) {
        int r = i >> 6;
        int s = rs[i];
        if (r < 63) s += rs[i + 64];
        if (r < 62) s += rs[i + 128];
        m1s[i] = (unsigned char)(s > 1);
    }
    __syncthreads();
    for (int i = t; i < 1024; i += 256) {
        int r = i >> 5, c = i & 31;
        int s = m1s[(2 * r) * 64 + 2 * c] + m1s[(2 * r) * 64 + 2 * c + 1]
              + m1s[(2 * r + 1) * 64 + 2 * c] + m1s[(2 * r + 1) * 64 + 2 * c + 1];
        m2s[i] = (unsigned char)(s > 1);
    }
    __syncthreads();
    for (int i = t; i < 1024; i += 256) g_m2[b * 1024 + i] = m2s[i];

    float* p1b = g_p1 + b * 32768;

    for (int pp = 0; pp < 4; pp++) {
        const int pos = pp * 256 + t;
        const int py = pos >> 5, px = pos & 31;
        const bool g2 = (m2s[pos] != 0);

        float patch[4][4];
        #pragma unroll
        for (int r = 0; r < 4; r++)
            #pragma unroll
            for (int c = 0; c < 4; c++)
                patch[r][c] = xs[(2 * py + r) * 66 + (2 * px + c)];

        bool mm[2][2];
        mm[0][0] = m1s[(2 * py) * 64 + 2 * px];
        mm[0][1] = m1s[(2 * py) * 64 + 2 * px + 1];
        mm[1][0] = m1s[(2 * py + 1) * 64 + 2 * px];
        mm[1][1] = m1s[(2 * py + 1) * 64 + 2 * px + 1];

        for (int co = 0; co < 32; co++) {
            float best = 0.f;
            if (g2) {
                float wv[9];
                #pragma unroll
                for (int k = 0; k < 9; k++) wv[k] = w1s[co * 9 + k];
                const float bias = b1s[co];
                #pragma unroll
                for (int dr = 0; dr < 2; dr++)
                    #pragma unroll
                    for (int dc = 0; dc < 2; dc++) {
                        if (mm[dr][dc]) {
                            float s = bias;
                            #pragma unroll
                            for (int kr = 0; kr < 3; kr++)
                                #pragma unroll
                                for (int kc = 0; kc < 3; kc++)
                                    s += wv[kr * 3 + kc] * patch[dr + kr][dc + kc];
                            best = fmaxf(best, s);
                        }
                    }
            }
            p1b[co * 1024 + pos] = best;
        }
    }
}

// ===========================================================================
// Kernel 2: conv2 via mma.sync bf16.  Grid = NB*8 (4 image rows per CTA),
// 128 threads (4 warps: 2 row-pairs x 2 co-halves), warp tile 64pos x 32co.
// ===========================================================================
#define C2_PSZ  (6 * 34 * 144)       // 29376
#define C2_BH   29376
#define C2_BL   34496
#define C2_BIAS 39616
#define C2_M2S  39872                // 6*32 = 192
#define C2_M3S  40064                // 4*32 = 128
#define C2_M4S  40192                // 2*16 = 32
#define C2_SMEM 40256

__device__ __forceinline__ void store_p2(int idx, float v) {
    __nv_bfloat16 hi = __float2bfloat16(v);
    __nv_bfloat16 lo = __float2bfloat16(v - __bfloat162float(hi));
    g_p2h[idx] = hi;
    g_p2l[idx] = lo;
}

__global__ __launch_bounds__(128, 4) void k_conv2m(const float* __restrict__ b2)
{
    extern __shared__ char smc[];
    const int bq = blockIdx.x;
    const int b = bq >> 3, q = bq & 7;
    const int tx = threadIdx.x;
    const int w = tx >> 5, lane = tx & 31;
    const int wr = w >> 1, wn = w & 1;        // row-pair, co-half
    const int g = lane >> 2, t = lane & 3;
    const int r0 = 4 * q;

    float* b2s = (float*)(smc + C2_BIAS);
    unsigned char* m2s = (unsigned char*)(smc + C2_M2S);
    unsigned char* m3s = (unsigned char*)(smc + C2_M3S);
    unsigned char* m4s = (unsigned char*)(smc + C2_M4S);

    for (int i = tx; i < C2_PSZ / 4; i += 128) ((uint32_t*)smc)[i] = 0;
    if (tx < 64) b2s[tx] = b2[tx];
    for (int i = tx; i < 192; i += 128) {      // m2 rows r0..r0+5 (clamped)
        int r = i >> 5, c = i & 31;
        int yr = r0 + r;
        m2s[i] = (yr < 32) ? g_m2[b * 1024 + yr * 32 + c] : (unsigned char)0;
    }
    __syncthreads();

    for (int i = tx; i < 128; i += 128) {      // m3 rows r0..r0+3
        int r = i >> 5, c = i & 31;
        int s = 0;
        #pragma unroll
        for (int dr = 0; dr < 3; dr++) {
            s += m2s[(r + dr) * 32 + c];
            if (c + 1 < 32) s += m2s[(r + dr) * 32 + c + 1];
            if (c + 2 < 32) s += m2s[(r + dr) * 32 + c + 2];
        }
        m3s[i] = (unsigned char)(s > 1);
    }
    {   // P fill rows r0-1 .. r0+4 (clamped), local row = y - r0 + 1
        const float* p1b = g_p1 + b * 32768;
        int y_lo = r0 - 1; if (y_lo < 0) y_lo = 0;
        int y_hi = r0 + 4; if (y_hi > 31) y_hi = 31;
        for (int y = y_lo; y <= y_hi; y++) {
            const float* row = p1b + y * 32;
            for (int i2 = tx; i2 < 1024; i2 += 128) {
                int ci = i2 >> 5, x = i2 & 31;
                float v = row[ci * 1024 + x];
                __nv_bfloat16 hi = __float2bfloat16(v);
                __nv_bfloat16 lo = __float2bfloat16(v - __bfloat162float(hi));
                char* blk = smc + ((y - r0 + 1) * 34 + (x + 1)) * 144;
                *(__nv_bfloat16*)(blk + 2 * ci) = hi;
                *(__nv_bfloat16*)(blk + 64 + 2 * ci) = lo;
            }
        }
    }
    __syncthreads();
    if (tx < 32) {                             // m4, pooled rows 2q, 2q+1 local
        int gyl = tx >> 4, gx = tx & 15;
        int s = m3s[(2 * gyl) * 32 + 2 * gx] + m3s[(2 * gyl) * 32 + 2 * gx + 1]
              + m3s[(2 * gyl + 1) * 32 + 2 * gx] + m3s[(2 * gyl + 1) * 32 + 2 * gx + 1];
        m4s[tx] = (unsigned char)(s > 1);
    }

    float acc[4][4][4];
    #pragma unroll
    for (int mt = 0; mt < 4; mt++)
        #pragma unroll
        for (int nt = 0; nt < 4; nt++)
            #pragma unroll
            for (int j = 0; j < 4; j++) acc[mt][nt][j] = 0.f;

    int base[4];
    #pragma unroll
    for (int mt = 0; mt < 4; mt++)
        base[mt] = (((2 * wr + (mt >> 1)) * 34) + (mt & 1) * 16 + g) * 144 + t * 4;

    const int bcol = (wn * 32 + g) * 80 + t * 4;

    for (int s = 0; s < 9; s++) {
        const int sy = s / 3, sx = s - sy * 3;
        __syncthreads();
        {   // stage B (all 64 co, both hi and lo)
            int co = tx >> 1, h2 = tx & 1;
            const uint4* sh = (const uint4*)((const char*)g_Bh + (s * 64 + co) * 64 + h2 * 32);
            uint4 v0 = sh[0], v1 = sh[1];
            uint4* dh = (uint4*)(smc + C2_BH + co * 80 + h2 * 32);
            dh[0] = v0; dh[1] = v1;
            const uint4* sl = (const uint4*)((const char*)g_Bl + (s * 64 + co) * 64 + h2 * 32);
            uint4 u0 = sl[0], u1 = sl[1];
            uint4* dl = (uint4*)(smc + C2_BL + co * 80 + h2 * 32);
            dl[0] = u0; dl[1] = u1;
        }
        __syncthreads();
        const int soff = (sy * 34 + sx) * 144;
        #pragma unroll
        for (int ks = 0; ks < 2; ks++) {
            // B fragments for this co-half (both precisions, reused by 2 terms)
            uint32_t Bh[4][2], Bl[4][2];
            {
                const char* bh = smc + C2_BH + bcol + ks * 32;
                const char* bl = smc + C2_BL + bcol + ks * 32;
                #pragma unroll
                for (int nt = 0; nt < 4; nt++) {
                    Bh[nt][0] = *(const uint32_t*)(bh + nt * 640);
                    Bh[nt][1] = *(const uint32_t*)(bh + nt * 640 + 16);
                    Bl[nt][0] = *(const uint32_t*)(bl + nt * 640);
                    Bl[nt][1] = *(const uint32_t*)(bl + nt * 640 + 16);
                }
            }
            uint32_t A[4][4];
            // A = hi
            #pragma unroll
            for (int mt = 0; mt < 4; mt++) {
                const char* pa = smc + base[mt] + soff + ks * 32;
                A[mt][0] = *(const uint32_t*)(pa);
                A[mt][1] = *(const uint32_t*)(pa + 8 * 144);
                A[mt][2] = *(const uint32_t*)(pa + 16);
                A[mt][3] = *(const uint32_t*)(pa + 8 * 144 + 16);
            }
            #pragma unroll
            for (int mt = 0; mt < 4; mt++)
                #pragma unroll
                for (int nt = 0; nt < 4; nt++)
                    mma16816(acc[mt][nt], A[mt], Bh[nt]);   // ah*bh
            #pragma unroll
            for (int mt = 0; mt < 4; mt++)
                #pragma unroll
                for (int nt = 0; nt < 4; nt++)
                    mma16816(acc[mt][nt], A[mt], Bl[nt]);   // ah*bl
            // A = lo
            #pragma unroll
            for (int mt = 0; mt < 4; mt++) {
                const char* pa = smc + base[mt] + soff + ks * 32 + 64;
                A[mt][0] = *(const uint32_t*)(pa);
                A[mt][1] = *(const uint32_t*)(pa + 8 * 144);
                A[mt][2] = *(const uint32_t*)(pa + 16);
                A[mt][3] = *(const uint32_t*)(pa + 8 * 144 + 16);
            }
            #pragma unroll
            for (int mt = 0; mt < 4; mt++)
                #pragma unroll
                for (int nt = 0; nt < 4; nt++)
                    mma16816(acc[mt][nt], A[mt], Bh[nt]);   // al*bh
        }
    }

    // epilogue: m3 gate + bias + relu -> pool -> m4 gate -> bf16 hi/lo store
    const int gy = 2 * q + wr;
    const int dbase = b * 16384 + gy * 16;
    #pragma unroll
    for (int mh = 0; mh < 2; mh++) {
        #pragma unroll
        for (int nt = 0; nt < 4; nt++) {
            const int co = wn * 32 + nt * 8 + 2 * t;
            const float bias0 = b2s[co];
            const float bias1 = b2s[co + 1];
            float v0[2], v1[2], v2[2], v3[2];
            #pragma unroll
            for (int mp = 0; mp < 2; mp++) {
                const int mt = mh + 2 * mp;
                const int mrow = (2 * wr + mp) * 32 + mh * 16 + g;
                const bool g3a = m3s[mrow] != 0;
                const bool g3b = m3s[mrow + 8] != 0;
                v0[mp] = g3a ? fmaxf(acc[mt][nt][0] + bias0, 0.f) : 0.f;
                v1[mp] = g3a ? fmaxf(acc[mt][nt][1] + bias1, 0.f) : 0.f;
                v2[mp] = g3b ? fmaxf(acc[mt][nt][2] + bias0, 0.f) : 0.f;
                v3[mp] = g3b ? fmaxf(acc[mt][nt][3] + bias1, 0.f) : 0.f;
            }
            float o0 = fmaxf(v0[0], v0[1]);
            float o1 = fmaxf(v1[0], v1[1]);
            float o2 = fmaxf(v2[0], v2[1]);
            float o3 = fmaxf(v3[0], v3[1]);
            o0 = fmaxf(o0, __shfl_xor_sync(0xffffffffu, o0, 4));
            o1 = fmaxf(o1, __shfl_xor_sync(0xffffffffu, o1, 4));
            o2 = fmaxf(o2, __shfl_xor_sync(0xffffffffu, o2, 4));
            o3 = fmaxf(o3, __shfl_xor_sync(0xffffffffu, o3, 4));
            if ((lane & 4) == 0) {
                const int gxa = mh * 8 + (g >> 1);
                const int gxb = gxa + 4;
                const bool g4a = m4s[wr * 16 + gxa] != 0;
                const bool g4b = m4s[wr * 16 + gxb] != 0;
                store_p2(dbase + co * 256 + gxa,       g4a ? o0 : 0.f);
                store_p2(dbase + (co + 1) * 256 + gxa, g4a ? o1 : 0.f);
                store_p2(dbase + co * 256 + gxb,       g4b ? o2 : 0.f);
                store_p2(dbase + (co + 1) * 256 + gxb, g4b ? o3 : 0.f);
            }
        }
    }
}

// ===========================================================================
// Kernel 3: FC1 via mma.sync bf16 (3-term hi/lo), global-direct fragments.
// ===========================================================================
__global__ __launch_bounds__(256) void k_fc1m()
{
    const int ks = blockIdx.x;
    const int tx = threadIdx.x;
    const int warp = tx >> 5, lane = tx & 31;
    const int g = lane >> 2, t = lane & 3;
    const int wm = warp >> 1, wn = warp & 1;
    const int row0 = wm * 64, col0 = wn * 64;
    const int k0 = ks * 128;

    float acc[4][8][4];
    #pragma unroll
    for (int mt = 0; mt < 4; mt++)
        #pragma unroll
        for (int nt = 0; nt < 8; nt++)
            #pragma unroll
            for (int j = 0; j < 4; j++) acc[mt][nt][j] = 0.f;

    #pragma unroll 2
    for (int kk = 0; kk < 8; kk++) {
        const int kb = k0 + kk * 16;
        uint32_t Ah[4][4], Al[4][4];
        #pragma unroll
        for (int mt = 0; mt < 4; mt++) {
            const int r = row0 + mt * 16 + g;
            const __nv_bfloat16* ph = g_p2h + r * 16384 + kb + 2 * t;
            const __nv_bfloat16* pl = g_p2l + r * 16384 + kb + 2 * t;
            Ah[mt][0] = *(const uint32_t*)(ph);
            Ah[mt][1] = *(const uint32_t*)(ph + 8 * 16384);
            Ah[mt][2] = *(const uint32_t*)(ph + 8);
            Ah[mt][3] = *(const uint32_t*)(ph + 8 * 16384 + 8);
            Al[mt][0] = *(const uint32_t*)(pl);
            Al[mt][1] = *(const uint32_t*)(pl + 8 * 16384);
            Al[mt][2] = *(const uint32_t*)(pl + 8);
            Al[mt][3] = *(const uint32_t*)(pl + 8 * 16384 + 8);
        }
        #pragma unroll
        for (int term = 0; term < 3; term++) {
            const __nv_bfloat16* wbase = (term == 1) ? g_Wl : g_Wh;
            uint32_t Bf[8][2];
            #pragma unroll
            for (int nt = 0; nt < 8; nt++) {
                const int j = col0 + nt * 8 + g;
                const __nv_bfloat16* pb = wbase + j * 16384 + kb + 2 * t;
                Bf[nt][0] = *(const uint32_t*)(pb);
                Bf[nt][1] = *(const uint32_t*)(pb + 8);
            }
            #pragma unroll
            for (int mt = 0; mt < 4; mt++) {
                const uint32_t* A = (term == 2) ? Al[mt] : Ah[mt];
                #pragma unroll
                for (int nt = 0; nt < 8; nt++)
                    mma16816(acc[mt][nt], A, Bf[nt]);
            }
        }
    }

    float* dst = g_part + ks * 32768;
    #pragma unroll
    for (int mt = 0; mt < 4; mt++) {
        const int r = row0 + mt * 16 + g;
        #pragma unroll
        for (int nt = 0; nt < 8; nt++) {
            const int c = col0 + nt * 8 + 2 * t;
            *(float2*)(dst + r * 128 + c)       = make_float2(acc[mt][nt][0], acc[mt][nt][1]);
            *(float2*)(dst + (r + 8) * 128 + c) = make_float2(acc[mt][nt][2], acc[mt][nt][3]);
        }
    }
}

// ===========================================================================
// Kernel 4: reduce 128 partials + bfc1 + relu + FC2 (512 threads)
// ===========================================================================
__global__ __launch_bounds__(512) void k_fc2(
    const float* __restrict__ bfc1, const float* __restrict__ Wfc2,
    const float* __restrict__ bfc2, float* __restrict__ out)
{
    __shared__ float part[4][128];
    __shared__ float hs[128];
    const int b = blockIdx.x, t = threadIdx.x;
    const int j = t & 127, seg = t >> 7;

    float s = 0.f;
    #pragma unroll 8
    for (int ks = seg * 32; ks < seg * 32 + 32; ks++)
        s += g_part[ks * 32768 + b * 128 + j];
    part[seg][j] = s;
    __syncthreads();

    if (t < 128) {
        float v = part[0][t] + part[1][t] + part[2][t] + part[3][t] + bfc1[t];
        hs[t] = fmaxf(v, 0.f);
    }
    __syncthreads();

    if (t < 10) {
        float a = bfc2[t];
        #pragma unroll 8
        for (int jj = 0; jj < 128; jj++) a += hs[jj] * Wfc2[t * 128 + jj];
        out[b * 10 + t] = a;
    }
}

// ===========================================================================
extern "C" void kernel_launch(void* const* d_in, const int* in_sizes, int n_in,
                              void* d_out, int out_size)
{
    const float* x    = (const float*)d_in[0];
    const int*   cmap = (const int*)  d_in[1];
    const float* W1   = (const float*)d_in[2];
    const float* b1   = (const float*)d_in[3];
    const float* W2   = (const float*)d_in[4];
    const float* b2   = (const float*)d_in[5];
    const float* Wfc1 = (const float*)d_in[6];
    const float* bfc1 = (const float*)d_in[7];
    const float* Wfc2 = (const float*)d_in[8];
    const float* bfc2 = (const float*)d_in[9];
    float* out = (float*)d_out;

    cudaFuncSetAttribute(k_conv2m, cudaFuncAttributeMaxDynamicSharedMemorySize, C2_SMEM);

    k_prep<<<72, 256>>>(W2);
    k_prep_fc1<<<8192, 256>>>(Wfc1);
    k_conv1<<<NB, 256>>>(x, cmap, W1, b1);
    k_conv2m<<<NB * 8, 128, C2_SMEM>>>(b2);
    k_fc1m<<<KSPLIT, 256>>>();
    k_fc2<<<NB, 512>>>(bfc1, Wfc2, bfc2, out);
}

// round 8
// speedup vs baseline: 2.0772x; 1.0330x over previous
#include <cuda_runtime.h>
#include <cuda_bf16.h>
#include <cstdint>

// ---------------------------------------------------------------------------
// SimpleCNN gated pipeline.  R7: conv2m mainloop de-bloated:
//   - B fragments pre-arranged in global (fragment-major), loaded as LDG.128
//   - A fragments via ldmatrix.x4
//   - 9-shift mainloop is __syncthreads()-free
// ---------------------------------------------------------------------------

#define NB 256

__device__ float          g_p1[NB * 32 * 32 * 32];
__device__ unsigned char  g_m2[NB * 32 * 32];
__device__ __nv_bfloat16  g_p2h[NB * 16384];
__device__ __nv_bfloat16  g_p2l[NB * 16384];
__device__ uint32_t       g_Bf[9 * 2 * 2 * 2 * 2 * 32 * 4];   // conv2 W fragments
__device__ __nv_bfloat16  g_Wh[128 * 16384];     // fc1 weights hi [j][k]
__device__ __nv_bfloat16  g_Wl[128 * 16384];
#define KSPLIT 128
__device__ float          g_part[KSPLIT * 256 * 128];

__device__ __forceinline__ void mma16816(float* d, const uint32_t* a, const uint32_t* b) {
    asm volatile(
        "mma.sync.aligned.m16n8k16.row.col.f32.bf16.bf16.f32 "
        "{%0,%1,%2,%3}, {%4,%5,%6,%7}, {%8,%9}, {%0,%1,%2,%3};"
        : "+f"(d[0]), "+f"(d[1]), "+f"(d[2]), "+f"(d[3])
        : "r"(a[0]), "r"(a[1]), "r"(a[2]), "r"(a[3]), "r"(b[0]), "r"(b[1]));
}
__device__ __forceinline__ uint32_t smem_u32(const void* p) {
    uint32_t a;
    asm("{ .reg .u64 t; cvta.to.shared.u64 t, %1; cvt.u32.u64 %0, t; }" : "=r"(a) : "l"(p));
    return a;
}
#define LDMX4(r, addr) \
    asm volatile("ldmatrix.sync.aligned.m8n8.x4.shared.b16 {%0,%1,%2,%3}, [%4];" \
        : "=r"((r)[0]), "=r"((r)[1]), "=r"((r)[2]), "=r"((r)[3]) : "r"(addr))

__device__ __forceinline__ unsigned short bfbits(__nv_bfloat16 h) {
    unsigned short s; memcpy(&s, &h, 2); return s;
}

// ===========================================================================
// Kernel 0a: W2 -> fragment-major bf16 hi/lo B for conv2m
// layout idx = ((((s*2+ks)*2+wn)*2+hl)*2+reg)*32*4 ... [lane][nt]
// ===========================================================================
__global__ void k_prepf(const float* __restrict__ W2)
{
    int i = blockIdx.x * 256 + threadIdx.x;      // 18432
    if (i >= 9 * 2 * 2 * 2 * 2 * 32 * 4) return;
    int nt   = i & 3;
    int lane = (i >> 2) & 31;
    int reg  = (i >> 7) & 1;
    int hl   = (i >> 8) & 1;
    int wn   = (i >> 9) & 1;
    int ks   = (i >> 10) & 1;
    int s    = i >> 11;
    int g = lane >> 2, t = lane & 3;
    int co  = wn * 32 + nt * 8 + g;
    int ci0 = ks * 16 + reg * 8 + 2 * t;
    float w0 = W2[co * 288 + ci0 * 9 + s];
    float w1 = W2[co * 288 + (ci0 + 1) * 9 + s];
    __nv_bfloat16 h0 = __float2bfloat16(w0);
    __nv_bfloat16 h1 = __float2bfloat16(w1);
    __nv_bfloat16 e0, e1;
    if (hl == 0) { e0 = h0; e1 = h1; }
    else {
        e0 = __float2bfloat16(w0 - __bfloat162float(h0));
        e1 = __float2bfloat16(w1 - __bfloat162float(h1));
    }
    g_Bf[i] = (uint32_t)bfbits(e0) | ((uint32_t)bfbits(e1) << 16);
}

// ===========================================================================
// Kernel 0b: split Wfc1 into bf16 hi/lo
// ===========================================================================
__global__ void k_prep_fc1(const float* __restrict__ Wfc1)
{
    int i = blockIdx.x * 256 + threadIdx.x;
    float w = Wfc1[i];
    __nv_bfloat16 hi = __float2bfloat16(w);
    __nv_bfloat16 lo = __float2bfloat16(w - __bfloat162float(hi));
    g_Wh[i] = hi;
    g_Wl[i] = lo;
}

// ===========================================================================
// Kernel 1: conv1 + gates + pool (unchanged scalar)
// ===========================================================================
__global__ __launch_bounds__(256) void k_conv1(
    const float* __restrict__ x, const int* __restrict__ cmap,
    const float* __restrict__ W1, const float* __restrict__ b1)
{
    __shared__ float xs[66 * 66];
    __shared__ unsigned char cs[64 * 64];
    __shared__ unsigned char rs[64 * 64];
    __shared__ unsigned char m1s[64 * 64];
    __shared__ unsigned char m2s[32 * 32];
    __shared__ float w1s[288];
    __shared__ float b1s[32];

    const int b = blockIdx.x, t = threadIdx.x;
    const float* xb = x + b * 4096;
    const int*   cb = cmap + b * 4096;

    for (int i = t; i < 66 * 66; i += 256) {
        int r = i / 66, c = i % 66;
        float v = 0.f;
        if (r >= 1 && r <= 64 && c >= 1 && c <= 64) v = xb[(r - 1) * 64 + (c - 1)];
        xs[i] = v;
    }
    for (int i = t; i < 4096; i += 256) cs[i] = (unsigned char)cb[i];
    for (int i = t; i < 288; i += 256) w1s[i] = W1[i];
    if (t < 32)  b1s[t] = b1[t];
    __syncthreads();

    for (int i = t; i < 4096; i += 256) {
        int c = i & 63;
        int s = cs[i];
        if (c < 63) s += cs[i + 1];
        if (c < 62) s += cs[i + 2];
        rs[i] = (unsigned char)s;
    }
    __syncthreads();
    for (int i = t; i < 4096; i += 256) {
        int r = i >> 6;
        int s = rs[i];
        if (r < 63) s += rs[i + 64];
        if (r < 62) s += rs[i + 128];
        m1s[i] = (unsigned char)(s > 1);
    }
    __syncthreads();
    for (int i = t; i < 1024; i += 256) {
        int r = i >> 5, c = i & 31;
        int s = m1s[(2 * r) * 64 + 2 * c] + m1s[(2 * r) * 64 + 2 * c + 1]
              + m1s[(2 * r + 1) * 64 + 2 * c] + m1s[(2 * r + 1) * 64 + 2 * c + 1];
        m2s[i] = (unsigned char)(s > 1);
    }
    __syncthreads();
    for (int i = t; i < 1024; i += 256) g_m2[b * 1024 + i] = m2s[i];

    float* p1b = g_p1 + b * 32768;

    for (int pp = 0; pp < 4; pp++) {
        const int pos = pp * 256 + t;
        const int py = pos >> 5, px = pos & 31;
        const bool g2 = (m2s[pos] != 0);

        float patch[4][4];
        #pragma unroll
        for (int r = 0; r < 4; r++)
            #pragma unroll
            for (int c = 0; c < 4; c++)
                patch[r][c] = xs[(2 * py + r) * 66 + (2 * px + c)];

        bool mm[2][2];
        mm[0][0] = m1s[(2 * py) * 64 + 2 * px];
        mm[0][1] = m1s[(2 * py) * 64 + 2 * px + 1];
        mm[1][0] = m1s[(2 * py + 1) * 64 + 2 * px];
        mm[1][1] = m1s[(2 * py + 1) * 64 + 2 * px + 1];

        for (int co = 0; co < 32; co++) {
            float best = 0.f;
            if (g2) {
                float wv[9];
                #pragma unroll
                for (int k = 0; k < 9; k++) wv[k] = w1s[co * 9 + k];
                const float bias = b1s[co];
                #pragma unroll
                for (int dr = 0; dr < 2; dr++)
                    #pragma unroll
                    for (int dc = 0; dc < 2; dc++) {
                        if (mm[dr][dc]) {
                            float s = bias;
                            #pragma unroll
                            for (int kr = 0; kr < 3; kr++)
                                #pragma unroll
                                for (int kc = 0; kc < 3; kc++)
                                    s += wv[kr * 3 + kc] * patch[dr + kr][dc + kc];
                            best = fmaxf(best, s);
                        }
                    }
            }
            p1b[co * 1024 + pos] = best;
        }
    }
}

// ===========================================================================
// Kernel 2: conv2 via mma.sync bf16.  Grid = NB*8, 128 threads (4 warps:
// 2 row-pairs x 2 co-halves), warp tile 64pos x 32co.
// Mainloop: ldmatrix A from smem, B fragments LDG.128 from global, no syncs.
// ===========================================================================
#define C2_PSZ  (6 * 34 * 144)       // 29376, P at smem offset 0
#define C2_BIAS 29376
#define C2_M2S  29632
#define C2_M3S  29824
#define C2_M4S  29952
#define C2_SMEM 30080

__device__ __forceinline__ void store_p2(int idx, float v) {
    __nv_bfloat16 hi = __float2bfloat16(v);
    __nv_bfloat16 lo = __float2bfloat16(v - __bfloat162float(hi));
    g_p2h[idx] = hi;
    g_p2l[idx] = lo;
}

__global__ __launch_bounds__(128, 4) void k_conv2m(const float* __restrict__ b2)
{
    extern __shared__ char smc[];
    const int bq = blockIdx.x;
    const int b = bq >> 3, q = bq & 7;
    const int tx = threadIdx.x;
    const int w = tx >> 5, lane = tx & 31;
    const int wr = w >> 1, wn = w & 1;
    const int g = lane >> 2, t = lane & 3;
    const int r0 = 4 * q;

    float* b2s = (float*)(smc + C2_BIAS);
    unsigned char* m2s = (unsigned char*)(smc + C2_M2S);
    unsigned char* m3s = (unsigned char*)(smc + C2_M3S);
    unsigned char* m4s = (unsigned char*)(smc + C2_M4S);

    for (int i = tx; i < C2_PSZ / 4; i += 128) ((uint32_t*)smc)[i] = 0;
    if (tx < 64) b2s[tx] = b2[tx];
    for (int i = tx; i < 192; i += 128) {
        int r = i >> 5, c = i & 31;
        int yr = r0 + r;
        m2s[i] = (yr < 32) ? g_m2[b * 1024 + yr * 32 + c] : (unsigned char)0;
    }
    __syncthreads();

    for (int i = tx; i < 128; i += 128) {
        int r = i >> 5, c = i & 31;
        int s = 0;
        #pragma unroll
        for (int dr = 0; dr < 3; dr++) {
            s += m2s[(r + dr) * 32 + c];
            if (c + 1 < 32) s += m2s[(r + dr) * 32 + c + 1];
            if (c + 2 < 32) s += m2s[(r + dr) * 32 + c + 2];
        }
        m3s[i] = (unsigned char)(s > 1);
    }
    {
        const float* p1b = g_p1 + b * 32768;
        int y_lo = r0 - 1; if (y_lo < 0) y_lo = 0;
        int y_hi = r0 + 4; if (y_hi > 31) y_hi = 31;
        for (int y = y_lo; y <= y_hi; y++) {
            const float* row = p1b + y * 32;
            for (int i2 = tx; i2 < 1024; i2 += 128) {
                int ci = i2 >> 5, x = i2 & 31;
                float v = row[ci * 1024 + x];
                __nv_bfloat16 hi = __float2bfloat16(v);
                __nv_bfloat16 lo = __float2bfloat16(v - __bfloat162float(hi));
                char* blk = smc + ((y - r0 + 1) * 34 + (x + 1)) * 144;
                *(__nv_bfloat16*)(blk + 2 * ci) = hi;
                *(__nv_bfloat16*)(blk + 64 + 2 * ci) = lo;
            }
        }
    }
    __syncthreads();
    if (tx < 32) {
        int gyl = tx >> 4, gx = tx & 15;
        int s = m3s[(2 * gyl) * 32 + 2 * gx] + m3s[(2 * gyl) * 32 + 2 * gx + 1]
              + m3s[(2 * gyl + 1) * 32 + 2 * gx] + m3s[(2 * gyl + 1) * 32 + 2 * gx + 1];
        m4s[tx] = (unsigned char)(s > 1);
    }
    __syncthreads();   // P + masks complete; mainloop below is sync-free

    float acc[4][4][4];
    #pragma unroll
    for (int mt = 0; mt < 4; mt++)
        #pragma unroll
        for (int nt = 0; nt < 4; nt++)
            #pragma unroll
            for (int j = 0; j < 4; j++) acc[mt][nt][j] = 0.f;

    // per-lane ldmatrix row addresses (x4: lanes 0-15 rows, 16-31 k-half 2)
    const uint32_t sb = smem_u32(smc);
    const int ml = lane & 15, kh = lane >> 4;
    uint32_t Abase[4];
    #pragma unroll
    for (int mt = 0; mt < 4; mt++)
        Abase[mt] = sb + (uint32_t)((((2 * wr + (mt >> 1)) * 34) + (mt & 1) * 16 + ml) * 144 + kh * 16);

    const uint4* pbase = (const uint4*)g_Bf;

    for (int s = 0; s < 9; s++) {
        const int sy = s / 3, sx = s - sy * 3;
        const uint32_t soff = (uint32_t)((sy * 34 + sx) * 144);
        #pragma unroll
        for (int ks = 0; ks < 2; ks++) {
            const int fo = ((s * 2 + ks) * 2 + wn) * 128 + lane;   // uint4 index
            uint4 bh0 = pbase[fo];
            uint4 bh1 = pbase[fo + 32];
            uint4 bl0 = pbase[fo + 64];
            uint4 bl1 = pbase[fo + 96];
            uint32_t Bh[4][2] = {{bh0.x, bh1.x}, {bh0.y, bh1.y}, {bh0.z, bh1.z}, {bh0.w, bh1.w}};
            uint32_t Bl[4][2] = {{bl0.x, bl1.x}, {bl0.y, bl1.y}, {bl0.z, bl1.z}, {bl0.w, bl1.w}};

            const uint32_t ao = soff + ks * 32;
            uint32_t A[4][4];
            #pragma unroll
            for (int mt = 0; mt < 4; mt++) LDMX4(A[mt], Abase[mt] + ao);
            #pragma unroll
            for (int mt = 0; mt < 4; mt++)
                #pragma unroll
                for (int nt = 0; nt < 4; nt++)
                    mma16816(acc[mt][nt], A[mt], Bh[nt]);      // ah*bh
            #pragma unroll
            for (int mt = 0; mt < 4; mt++)
                #pragma unroll
                for (int nt = 0; nt < 4; nt++)
                    mma16816(acc[mt][nt], A[mt], Bl[nt]);      // ah*bl
            #pragma unroll
            for (int mt = 0; mt < 4; mt++) LDMX4(A[mt], Abase[mt] + ao + 64);
            #pragma unroll
            for (int mt = 0; mt < 4; mt++)
                #pragma unroll
                for (int nt = 0; nt < 4; nt++)
                    mma16816(acc[mt][nt], A[mt], Bh[nt]);      // al*bh
        }
    }

    // epilogue: m3 gate + bias + relu -> pool -> m4 gate -> bf16 hi/lo store
    const int gy = 2 * q + wr;
    const int dbase = b * 16384 + gy * 16;
    #pragma unroll
    for (int mh = 0; mh < 2; mh++) {
        #pragma unroll
        for (int nt = 0; nt < 4; nt++) {
            const int co = wn * 32 + nt * 8 + 2 * t;
            const float bias0 = b2s[co];
            const float bias1 = b2s[co + 1];
            float v0[2], v1[2], v2[2], v3[2];
            #pragma unroll
            for (int mp = 0; mp < 2; mp++) {
                const int mt = mh + 2 * mp;
                const int mrow = (2 * wr + mp) * 32 + mh * 16 + g;
                const bool g3a = m3s[mrow] != 0;
                const bool g3b = m3s[mrow + 8] != 0;
                v0[mp] = g3a ? fmaxf(acc[mt][nt][0] + bias0, 0.f) : 0.f;
                v1[mp] = g3a ? fmaxf(acc[mt][nt][1] + bias1, 0.f) : 0.f;
                v2[mp] = g3b ? fmaxf(acc[mt][nt][2] + bias0, 0.f) : 0.f;
                v3[mp] = g3b ? fmaxf(acc[mt][nt][3] + bias1, 0.f) : 0.f;
            }
            float o0 = fmaxf(v0[0], v0[1]);
            float o1 = fmaxf(v1[0], v1[1]);
            float o2 = fmaxf(v2[0], v2[1]);
            float o3 = fmaxf(v3[0], v3[1]);
            o0 = fmaxf(o0, __shfl_xor_sync(0xffffffffu, o0, 4));
            o1 = fmaxf(o1, __shfl_xor_sync(0xffffffffu, o1, 4));
            o2 = fmaxf(o2, __shfl_xor_sync(0xffffffffu, o2, 4));
            o3 = fmaxf(o3, __shfl_xor_sync(0xffffffffu, o3, 4));
            if ((lane & 4) == 0) {
                const int gxa = mh * 8 + (g >> 1);
                const int gxb = gxa + 4;
                const bool g4a = m4s[wr * 16 + gxa] != 0;
                const bool g4b = m4s[wr * 16 + gxb] != 0;
                store_p2(dbase + co * 256 + gxa,       g4a ? o0 : 0.f);
                store_p2(dbase + (co + 1) * 256 + gxa, g4a ? o1 : 0.f);
                store_p2(dbase + co * 256 + gxb,       g4b ? o2 : 0.f);
                store_p2(dbase + (co + 1) * 256 + gxb, g4b ? o3 : 0.f);
            }
        }
    }
}

// ===========================================================================
// Kernel 3: FC1 via mma.sync bf16 (3-term hi/lo), global-direct fragments.
// ===========================================================================
__global__ __launch_bounds__(256) void k_fc1m()
{
    const int ks = blockIdx.x;
    const int tx = threadIdx.x;
    const int warp = tx >> 5, lane = tx & 31;
    const int g = lane >> 2, t = lane & 3;
    const int wm = warp >> 1, wn = warp & 1;
    const int row0 = wm * 64, col0 = wn * 64;
    const int k0 = ks * 128;

    float acc[4][8][4];
    #pragma unroll
    for (int mt = 0; mt < 4; mt++)
        #pragma unroll
        for (int nt = 0; nt < 8; nt++)
            #pragma unroll
            for (int j = 0; j < 4; j++) acc[mt][nt][j] = 0.f;

    #pragma unroll 2
    for (int kk = 0; kk < 8; kk++) {
        const int kb = k0 + kk * 16;
        uint32_t Ah[4][4], Al[4][4];
        #pragma unroll
        for (int mt = 0; mt < 4; mt++) {
            const int r = row0 + mt * 16 + g;
            const __nv_bfloat16* ph = g_p2h + r * 16384 + kb + 2 * t;
            const __nv_bfloat16* pl = g_p2l + r * 16384 + kb + 2 * t;
            Ah[mt][0] = *(const uint32_t*)(ph);
            Ah[mt][1] = *(const uint32_t*)(ph + 8 * 16384);
            Ah[mt][2] = *(const uint32_t*)(ph + 8);
            Ah[mt][3] = *(const uint32_t*)(ph + 8 * 16384 + 8);
            Al[mt][0] = *(const uint32_t*)(pl);
            Al[mt][1] = *(const uint32_t*)(pl + 8 * 16384);
            Al[mt][2] = *(const uint32_t*)(pl + 8);
            Al[mt][3] = *(const uint32_t*)(pl + 8 * 16384 + 8);
        }
        #pragma unroll
        for (int term = 0; term < 3; term++) {
            const __nv_bfloat16* wbase = (term == 1) ? g_Wl : g_Wh;
            uint32_t Bf[8][2];
            #pragma unroll
            for (int nt = 0; nt < 8; nt++) {
                const int j = col0 + nt * 8 + g;
                const __nv_bfloat16* pb = wbase + j * 16384 + kb + 2 * t;
                Bf[nt][0] = *(const uint32_t*)(pb);
                Bf[nt][1] = *(const uint32_t*)(pb + 8);
            }
            #pragma unroll
            for (int mt = 0; mt < 4; mt++) {
                const uint32_t* A = (term == 2) ? Al[mt] : Ah[mt];
                #pragma unroll
                for (int nt = 0; nt < 8; nt++)
                    mma16816(acc[mt][nt], A, Bf[nt]);
            }
        }
    }

    float* dst = g_part + ks * 32768;
    #pragma unroll
    for (int mt = 0; mt < 4; mt++) {
        const int r = row0 + mt * 16 + g;
        #pragma unroll
        for (int nt = 0; nt < 8; nt++) {
            const int c = col0 + nt * 8 + 2 * t;
            *(float2*)(dst + r * 128 + c)       = make_float2(acc[mt][nt][0], acc[mt][nt][1]);
            *(float2*)(dst + (r + 8) * 128 + c) = make_float2(acc[mt][nt][2], acc[mt][nt][3]);
        }
    }
}

// ===========================================================================
// Kernel 4: reduce 128 partials + bfc1 + relu + FC2 (512 threads)
// ===========================================================================
__global__ __launch_bounds__(512) void k_fc2(
    const float* __restrict__ bfc1, const float* __restrict__ Wfc2,
    const float* __restrict__ bfc2, float* __restrict__ out)
{
    __shared__ float part[4][128];
    __shared__ float hs[128];
    const int b = blockIdx.x, t = threadIdx.x;
    const int j = t & 127, seg = t >> 7;

    float s = 0.f;
    #pragma unroll 8
    for (int ks = seg * 32; ks < seg * 32 + 32; ks++)
        s += g_part[ks * 32768 + b * 128 + j];
    part[seg][j] = s;
    __syncthreads();

    if (t < 128) {
        float v = part[0][t] + part[1][t] + part[2][t] + part[3][t] + bfc1[t];
        hs[t] = fmaxf(v, 0.f);
    }
    __syncthreads();

    if (t < 10) {
        float a = bfc2[t];
        #pragma unroll 8
        for (int jj = 0; jj < 128; jj++) a += hs[jj] * Wfc2[t * 128 + jj];
        out[b * 10 + t] = a;
    }
}

// ===========================================================================
extern "C" void kernel_launch(void* const* d_in, const int* in_sizes, int n_in,
                              void* d_out, int out_size)
{
    const float* x    = (const float*)d_in[0];
    const int*   cmap = (const int*)  d_in[1];
    const float* W1   = (const float*)d_in[2];
    const float* b1   = (const float*)d_in[3];
    const float* W2   = (const float*)d_in[4];
    const float* b2   = (const float*)d_in[5];
    const float* Wfc1 = (const float*)d_in[6];
    const float* bfc1 = (const float*)d_in[7];
    const float* Wfc2 = (const float*)d_in[8];
    const float* bfc2 = (const float*)d_in[9];
    float* out = (float*)d_out;

    cudaFuncSetAttribute(k_conv2m, cudaFuncAttributeMaxDynamicSharedMemorySize, C2_SMEM);

    k_prepf<<<72, 256>>>(W2);
    k_prep_fc1<<<8192, 256>>>(Wfc1);
    k_conv1<<<NB, 256>>>(x, cmap, W1, b1);
    k_conv2m<<<NB * 8, 128, C2_SMEM>>>(b2);
    k_fc1m<<<KSPLIT, 256>>>();
    k_fc2<<<NB, 512>>>(bfc1, Wfc2, bfc2, out);
}

// round 9
// speedup vs baseline: 2.0904x; 1.0064x over previous
#include <cuda_runtime.h>
#include <cuda_bf16.h>
#include <cstdint>

// ---------------------------------------------------------------------------
// SimpleCNN gated pipeline.  R7: conv2m mainloop de-bloated:
//   - B fragments pre-arranged in global (fragment-major), loaded as LDG.128
//   - A fragments via ldmatrix.x4
//   - 9-shift mainloop is __syncthreads()-free
// ---------------------------------------------------------------------------

#define NB 256

__device__ float          g_p1[NB * 32 * 32 * 32];
__device__ unsigned char  g_m2[NB * 32 * 32];
__device__ __nv_bfloat16  g_p2h[NB * 16384];
__device__ __nv_bfloat16  g_p2l[NB * 16384];
__device__ uint32_t       g_Bf[9 * 2 * 2 * 2 * 2 * 32 * 4];   // conv2 W fragments
__device__ __nv_bfloat16  g_Wh[128 * 16384];     // fc1 weights hi [j][k]
__device__ __nv_bfloat16  g_Wl[128 * 16384];
#define KSPLIT 128
__device__ float          g_part[KSPLIT * 256 * 128];

__device__ __forceinline__ void mma16816(float* d, const uint32_t* a, const uint32_t* b) {
    asm volatile(
        "mma.sync.aligned.m16n8k16.row.col.f32.bf16.bf16.f32 "
        "{%0,%1,%2,%3}, {%4,%5,%6,%7}, {%8,%9}, {%0,%1,%2,%3};"
        : "+f"(d[0]), "+f"(d[1]), "+f"(d[2]), "+f"(d[3])
        : "r"(a[0]), "r"(a[1]), "r"(a[2]), "r"(a[3]), "r"(b[0]), "r"(b[1]));
}
__device__ __forceinline__ uint32_t smem_u32(const void* p) {
    uint32_t a;
    asm("{ .reg .u64 t; cvta.to.shared.u64 t, %1; cvt.u32.u64 %0, t; }" : "=r"(a) : "l"(p));
    return a;
}
#define LDMX4(r, addr) \
    asm volatile("ldmatrix.sync.aligned.m8n8.x4.shared.b16 {%0,%1,%2,%3}, [%4];" \
        : "=r"((r)[0]), "=r"((r)[1]), "=r"((r)[2]), "=r"((r)[3]) : "r"(addr))

__device__ __forceinline__ unsigned short bfbits(__nv_bfloat16 h) {
    unsigned short s; memcpy(&s, &h, 2); return s;
}

// ===========================================================================
// Kernel 0a: W2 -> fragment-major bf16 hi/lo B for conv2m
// layout idx = ((((s*2+ks)*2+wn)*2+hl)*2+reg)*32*4 ... [lane][nt]
// ===========================================================================
__global__ void k_prepf(const float* __restrict__ W2)
{
    int i = blockIdx.x * 256 + threadIdx.x;      // 18432
    if (i >= 9 * 2 * 2 * 2 * 2 * 32 * 4) return;
    int nt   = i & 3;
    int lane = (i >> 2) & 31;
    int reg  = (i >> 7) & 1;
    int hl   = (i >> 8) & 1;
    int wn   = (i >> 9) & 1;
    int ks   = (i >> 10) & 1;
    int s    = i >> 11;
    int g = lane >> 2, t = lane & 3;
    int co  = wn * 32 + nt * 8 + g;
    int ci0 = ks * 16 + reg * 8 + 2 * t;
    float w0 = W2[co * 288 + ci0 * 9 + s];
    float w1 = W2[co * 288 + (ci0 + 1) * 9 + s];
    __nv_bfloat16 h0 = __float2bfloat16(w0);
    __nv_bfloat16 h1 = __float2bfloat16(w1);
    __nv_bfloat16 e0, e1;
    if (hl == 0) { e0 = h0; e1 = h1; }
    else {
        e0 = __float2bfloat16(w0 - __bfloat162float(h0));
        e1 = __float2bfloat16(w1 - __bfloat162float(h1));
    }
    g_Bf[i] = (uint32_t)bfbits(e0) | ((uint32_t)bfbits(e1) << 16);
}

// ===========================================================================
// Kernel 0b: split Wfc1 into bf16 hi/lo
// ===========================================================================
__global__ void k_prep_fc1(const float* __restrict__ Wfc1)
{
    int i = blockIdx.x * 256 + threadIdx.x;
    float w = Wfc1[i];
    __nv_bfloat16 hi = __float2bfloat16(w);
    __nv_bfloat16 lo = __float2bfloat16(w - __bfloat162float(hi));
    g_Wh[i] = hi;
    g_Wl[i] = lo;
}

// ===========================================================================
// Kernel 1: conv1 + gates + pool (unchanged scalar)
// ===========================================================================
__global__ __launch_bounds__(256) void k_conv1(
    const float* __restrict__ x, const int* __restrict__ cmap,
    const float* __restrict__ W1, const float* __restrict__ b1)
{
    __shared__ float xs[66 * 66];
    __shared__ unsigned char cs[64 * 64];
    __shared__ unsigned char rs[64 * 64];
    __shared__ unsigned char m1s[64 * 64];
    __shared__ unsigned char m2s[32 * 32];
    __shared__ float w1s[288];
    __shared__ float b1s[32];

    const int b = blockIdx.x, t = threadIdx.x;
    const float* xb = x + b * 4096;
    const int*   cb = cmap + b * 4096;

    for (int i = t; i < 66 * 66; i += 256) {
        int r = i / 66, c = i % 66;
        float v = 0.f;
        if (r >= 1 && r <= 64 && c >= 1 && c <= 64) v = xb[(r - 1) * 64 + (c - 1)];
        xs[i] = v;
    }
    for (int i = t; i < 4096; i += 256) cs[i] = (unsigned char)cb[i];
    for (int i = t; i < 288; i += 256) w1s[i] = W1[i];
    if (t < 32)  b1s[t] = b1[t];
    __syncthreads();

    for (int i = t; i < 4096; i += 256) {
        int c = i & 63;
        int s = cs[i];
        if (c < 63) s += cs[i + 1];
        if (c < 62) s += cs[i + 2];
        rs[i] = (unsigned char)s;
    }
    __syncthreads();
    for (int i = t; i < 4096; i += 256) {
        int r = i >> 6;
        int s = rs[i];
        if (r < 63) s += rs[i + 64];
        if (r < 62) s += rs[i + 128];
        m1s[i] = (unsigned char)(s > 1);
    }
    __syncthreads();
    for (int i = t; i < 1024; i += 256) {
        int r = i >> 5, c = i & 31;
        int s = m1s[(2 * r) * 64 + 2 * c] + m1s[(2 * r) * 64 + 2 * c + 1]
              + m1s[(2 * r + 1) * 64 + 2 * c] + m1s[(2 * r + 1) * 64 + 2 * c + 1];
        m2s[i] = (unsigned char)(s > 1);
    }
    __syncthreads();
    for (int i = t; i < 1024; i += 256) g_m2[b * 1024 + i] = m2s[i];

    float* p1b = g_p1 + b * 32768;

    for (int pp = 0; pp < 4; pp++) {
        const int pos = pp * 256 + t;
        const int py = pos >> 5, px = pos & 31;
        const bool g2 = (m2s[pos] != 0);

        float patch[4][4];
        #pragma unroll
        for (int r = 0; r < 4; r++)
            #pragma unroll
            for (int c = 0; c < 4; c++)
                patch[r][c] = xs[(2 * py + r) * 66 + (2 * px + c)];

        bool mm[2][2];
        mm[0][0] = m1s[(2 * py) * 64 + 2 * px];
        mm[0][1] = m1s[(2 * py) * 64 + 2 * px + 1];
        mm[1][0] = m1s[(2 * py + 1) * 64 + 2 * px];
        mm[1][1] = m1s[(2 * py + 1) * 64 + 2 * px + 1];

        for (int co = 0; co < 32; co++) {
            float best = 0.f;
            if (g2) {
                float wv[9];
                #pragma unroll
                for (int k = 0; k < 9; k++) wv[k] = w1s[co * 9 + k];
                const float bias = b1s[co];
                #pragma unroll
                for (int dr = 0; dr < 2; dr++)
                    #pragma unroll
                    for (int dc = 0; dc < 2; dc++) {
                        if (mm[dr][dc]) {
                            float s = bias;
                            #pragma unroll
                            for (int kr = 0; kr < 3; kr++)
                                #pragma unroll
                                for (int kc = 0; kc < 3; kc++)
                                    s += wv[kr * 3 + kc] * patch[dr + kr][dc + kc];
                            best = fmaxf(best, s);
                        }
                    }
            }
            p1b[co * 1024 + pos] = best;
        }
    }
}

// ===========================================================================
// Kernel 2: conv2 via mma.sync bf16.  Grid = NB*8, 128 threads (4 warps:
// 2 row-pairs x 2 co-halves), warp tile 64pos x 32co.
// Mainloop: ldmatrix A from smem, B fragments LDG.128 from global, no syncs.
// ===========================================================================
#define C2_PSZ  (6 * 34 * 144)       // 29376, P at smem offset 0
#define C2_BIAS 29376
#define C2_M2S  29632
#define C2_M3S  29824
#define C2_M4S  29952
#define C2_SMEM 30080

__device__ __forceinline__ void store_p2(int idx, float v) {
    __nv_bfloat16 hi = __float2bfloat16(v);
    __nv_bfloat16 lo = __float2bfloat16(v - __bfloat162float(hi));
    g_p2h[idx] = hi;
    g_p2l[idx] = lo;
}

__global__ __launch_bounds__(128, 4) void k_conv2m(const float* __restrict__ b2)
{
    extern __shared__ char smc[];
    const int bq = blockIdx.x;
    const int b = bq >> 3, q = bq & 7;
    const int tx = threadIdx.x;
    const int w = tx >> 5, lane = tx & 31;
    const int wr = w >> 1, wn = w & 1;
    const int g = lane >> 2, t = lane & 3;
    const int r0 = 4 * q;

    float* b2s = (float*)(smc + C2_BIAS);
    unsigned char* m2s = (unsigned char*)(smc + C2_M2S);
    unsigned char* m3s = (unsigned char*)(smc + C2_M3S);
    unsigned char* m4s = (unsigned char*)(smc + C2_M4S);

    for (int i = tx; i < C2_PSZ / 4; i += 128) ((uint32_t*)smc)[i] = 0;
    if (tx < 64) b2s[tx] = b2[tx];
    for (int i = tx; i < 192; i += 128) {
        int r = i >> 5, c = i & 31;
        int yr = r0 + r;
        m2s[i] = (yr < 32) ? g_m2[b * 1024 + yr * 32 + c] : (unsigned char)0;
    }
    __syncthreads();

    for (int i = tx; i < 128; i += 128) {
        int r = i >> 5, c = i & 31;
        int s = 0;
        #pragma unroll
        for (int dr = 0; dr < 3; dr++) {
            s += m2s[(r + dr) * 32 + c];
            if (c + 1 < 32) s += m2s[(r + dr) * 32 + c + 1];
            if (c + 2 < 32) s += m2s[(r + dr) * 32 + c + 2];
        }
        m3s[i] = (unsigned char)(s > 1);
    }
    {
        const float* p1b = g_p1 + b * 32768;
        int y_lo = r0 - 1; if (y_lo < 0) y_lo = 0;
        int y_hi = r0 + 4; if (y_hi > 31) y_hi = 31;
        for (int y = y_lo; y <= y_hi; y++) {
            const float* row = p1b + y * 32;
            for (int i2 = tx; i2 < 1024; i2 += 128) {
                int ci = i2 >> 5, x = i2 & 31;
                float v = row[ci * 1024 + x];
                __nv_bfloat16 hi = __float2bfloat16(v);
                __nv_bfloat16 lo = __float2bfloat16(v - __bfloat162float(hi));
                char* blk = smc + ((y - r0 + 1) * 34 + (x + 1)) * 144;
                *(__nv_bfloat16*)(blk + 2 * ci) = hi;
                *(__nv_bfloat16*)(blk + 64 + 2 * ci) = lo;
            }
        }
    }
    __syncthreads();
    if (tx < 32) {
        int gyl = tx >> 4, gx = tx & 15;
        int s = m3s[(2 * gyl) * 32 + 2 * gx] + m3s[(2 * gyl) * 32 + 2 * gx + 1]
              + m3s[(2 * gyl + 1) * 32 + 2 * gx] + m3s[(2 * gyl + 1) * 32 + 2 * gx + 1];
        m4s[tx] = (unsigned char)(s > 1);
    }
    __syncthreads();   // P + masks complete; mainloop below is sync-free

    float acc[4][4][4];
    #pragma unroll
    for (int mt = 0; mt < 4; mt++)
        #pragma unroll
        for (int nt = 0; nt < 4; nt++)
            #pragma unroll
            for (int j = 0; j < 4; j++) acc[mt][nt][j] = 0.f;

    // per-lane ldmatrix row addresses (x4: lanes 0-15 rows, 16-31 k-half 2)
    const uint32_t sb = smem_u32(smc);
    const int ml = lane & 15, kh = lane >> 4;
    uint32_t Abase[4];
    #pragma unroll
    for (int mt = 0; mt < 4; mt++)
        Abase[mt] = sb + (uint32_t)((((2 * wr + (mt >> 1)) * 34) + (mt & 1) * 16 + ml) * 144 + kh * 16);

    const uint4* pbase = (const uint4*)g_Bf;

    for (int s = 0; s < 9; s++) {
        const int sy = s / 3, sx = s - sy * 3;
        const uint32_t soff = (uint32_t)((sy * 34 + sx) * 144);
        #pragma unroll
        for (int ks = 0; ks < 2; ks++) {
            const int fo = ((s * 2 + ks) * 2 + wn) * 128 + lane;   // uint4 index
            uint4 bh0 = pbase[fo];
            uint4 bh1 = pbase[fo + 32];
            uint4 bl0 = pbase[fo + 64];
            uint4 bl1 = pbase[fo + 96];
            uint32_t Bh[4][2] = {{bh0.x, bh1.x}, {bh0.y, bh1.y}, {bh0.z, bh1.z}, {bh0.w, bh1.w}};
            uint32_t Bl[4][2] = {{bl0.x, bl1.x}, {bl0.y, bl1.y}, {bl0.z, bl1.z}, {bl0.w, bl1.w}};

            const uint32_t ao = soff + ks * 32;
            uint32_t A[4][4];
            #pragma unroll
            for (int mt = 0; mt < 4; mt++) LDMX4(A[mt], Abase[mt] + ao);
            #pragma unroll
            for (int mt = 0; mt < 4; mt++)
                #pragma unroll
                for (int nt = 0; nt < 4; nt++)
                    mma16816(acc[mt][nt], A[mt], Bh[nt]);      // ah*bh
            #pragma unroll
            for (int mt = 0; mt < 4; mt++)
                #pragma unroll
                for (int nt = 0; nt < 4; nt++)
                    mma16816(acc[mt][nt], A[mt], Bl[nt]);      // ah*bl
            #pragma unroll
            for (int mt = 0; mt < 4; mt++) LDMX4(A[mt], Abase[mt] + ao + 64);
            #pragma unroll
            for (int mt = 0; mt < 4; mt++)
                #pragma unroll
                for (int nt = 0; nt < 4; nt++)
                    mma16816(acc[mt][nt], A[mt], Bh[nt]);      // al*bh
        }
    }

    // epilogue: m3 gate + bias + relu -> pool -> m4 gate -> bf16 hi/lo store
    const int gy = 2 * q + wr;
    const int dbase = b * 16384 + gy * 16;
    #pragma unroll
    for (int mh = 0; mh < 2; mh++) {
        #pragma unroll
        for (int nt = 0; nt < 4; nt++) {
            const int co = wn * 32 + nt * 8 + 2 * t;
            const float bias0 = b2s[co];
            const float bias1 = b2s[co + 1];
            float v0[2], v1[2], v2[2], v3[2];
            #pragma unroll
            for (int mp = 0; mp < 2; mp++) {
                const int mt = mh + 2 * mp;
                const int mrow = (2 * wr + mp) * 32 + mh * 16 + g;
                const bool g3a = m3s[mrow] != 0;
                const bool g3b = m3s[mrow + 8] != 0;
                v0[mp] = g3a ? fmaxf(acc[mt][nt][0] + bias0, 0.f) : 0.f;
                v1[mp] = g3a ? fmaxf(acc[mt][nt][1] + bias1, 0.f) : 0.f;
                v2[mp] = g3b ? fmaxf(acc[mt][nt][2] + bias0, 0.f) : 0.f;
                v3[mp] = g3b ? fmaxf(acc[mt][nt][3] + bias1, 0.f) : 0.f;
            }
            float o0 = fmaxf(v0[0], v0[1]);
            float o1 = fmaxf(v1[0], v1[1]);
            float o2 = fmaxf(v2[0], v2[1]);
            float o3 = fmaxf(v3[0], v3[1]);
            o0 = fmaxf(o0, __shfl_xor_sync(0xffffffffu, o0, 4));
            o1 = fmaxf(o1, __shfl_xor_sync(0xffffffffu, o1, 4));
            o2 = fmaxf(o2, __shfl_xor_sync(0xffffffffu, o2, 4));
            o3 = fmaxf(o3, __shfl_xor_sync(0xffffffffu, o3, 4));
            if ((lane & 4) == 0) {
                const int gxa = mh * 8 + (g >> 1);
                const int gxb = gxa + 4;
                const bool g4a = m4s[wr * 16 + gxa] != 0;
                const bool g4b = m4s[wr * 16 + gxb] != 0;
                store_p2(dbase + co * 256 + gxa,       g4a ? o0 : 0.f);
                store_p2(dbase + (co + 1) * 256 + gxa, g4a ? o1 : 0.f);
                store_p2(dbase + co * 256 + gxb,       g4b ? o2 : 0.f);
                store_p2(dbase + (co + 1) * 256 + gxb, g4b ? o3 : 0.f);
            }
        }
    }
}

// ===========================================================================
// Kernel 3: FC1 via mma.sync bf16 (3-term hi/lo), global-direct fragments.
// ===========================================================================
__global__ __launch_bounds__(256) void k_fc1m()
{
    const int ks = blockIdx.x;
    const int tx = threadIdx.x;
    const int warp = tx >> 5, lane = tx & 31;
    const int g = lane >> 2, t = lane & 3;
    const int wm = warp >> 1, wn = warp & 1;
    const int row0 = wm * 64, col0 = wn * 64;
    const int k0 = ks * 128;

    float acc[4][8][4];
    #pragma unroll
    for (int mt = 0; mt < 4; mt++)
        #pragma unroll
        for (int nt = 0; nt < 8; nt++)
            #pragma unroll
            for (int j = 0; j < 4; j++) acc[mt][nt][j] = 0.f;

    #pragma unroll 2
    for (int kk = 0; kk < 8; kk++) {
        const int kb = k0 + kk * 16;
        uint32_t Ah[4][4], Al[4][4];
        #pragma unroll
        for (int mt = 0; mt < 4; mt++) {
            const int r = row0 + mt * 16 + g;
            const __nv_bfloat16* ph = g_p2h + r * 16384 + kb + 2 * t;
            const __nv_bfloat16* pl = g_p2l + r * 16384 + kb + 2 * t;
            Ah[mt][0] = *(const uint32_t*)(ph);
            Ah[mt][1] = *(const uint32_t*)(ph + 8 * 16384);
            Ah[mt][2] = *(const uint32_t*)(ph + 8);
            Ah[mt][3] = *(const uint32_t*)(ph + 8 * 16384 + 8);
            Al[mt][0] = *(const uint32_t*)(pl);
            Al[mt][1] = *(const uint32_t*)(pl + 8 * 16384);
            Al[mt][2] = *(const uint32_t*)(pl + 8);
            Al[mt][3] = *(const uint32_t*)(pl + 8 * 16384 + 8);
        }
        #pragma unroll
        for (int term = 0; term < 3; term++) {
            const __nv_bfloat16* wbase = (term == 1) ? g_Wl : g_Wh;
            uint32_t Bf[8][2];
            #pragma unroll
            for (int nt = 0; nt < 8; nt++) {
                const int j = col0 + nt * 8 + g;
                const __nv_bfloat16* pb = wbase + j * 16384 + kb + 2 * t;
                Bf[nt][0] = *(const uint32_t*)(pb);
                Bf[nt][1] = *(const uint32_t*)(pb + 8);
            }
            #pragma unroll
            for (int mt = 0; mt < 4; mt++) {
                const uint32_t* A = (term == 2) ? Al[mt] : Ah[mt];
                #pragma unroll
                for (int nt = 0; nt < 8; nt++)
                    mma16816(acc[mt][nt], A, Bf[nt]);
            }
        }
    }

    float* dst = g_part + ks * 32768;
    #pragma unroll
    for (int mt = 0; mt < 4; mt++) {
        const int r = row0 + mt * 16 + g;
        #pragma unroll
        for (int nt = 0; nt < 8; nt++) {
            const int c = col0 + nt * 8 + 2 * t;
            *(float2*)(dst + r * 128 + c)       = make_float2(acc[mt][nt][0], acc[mt][nt][1]);
            *(float2*)(dst + (r + 8) * 128 + c) = make_float2(acc[mt][nt][2], acc[mt][nt][3]);
        }
    }
}

// ===========================================================================
// Kernel 4: reduce 128 partials + bfc1 + relu + FC2 (512 threads)
// ===========================================================================
__global__ __launch_bounds__(512) void k_fc2(
    const float* __restrict__ bfc1, const float* __restrict__ Wfc2,
    const float* __restrict__ bfc2, float* __restrict__ out)
{
    __shared__ float part[4][128];
    __shared__ float hs[128];
    const int b = blockIdx.x, t = threadIdx.x;
    const int j = t & 127, seg = t >> 7;

    float s = 0.f;
    #pragma unroll 8
    for (int ks = seg * 32; ks < seg * 32 + 32; ks++)
        s += g_part[ks * 32768 + b * 128 + j];
    part[seg][j] = s;
    __syncthreads();

    if (t < 128) {
        float v = part[0][t] + part[1][t] + part[2][t] + part[3][t] + bfc1[t];
        hs[t] = fmaxf(v, 0.f);
    }
    __syncthreads();

    if (t < 10) {
        float a = bfc2[t];
        #pragma unroll 8
        for (int jj = 0; jj < 128; jj++) a += hs[jj] * Wfc2[t * 128 + jj];
        out[b * 10 + t] = a;
    }
}

// ===========================================================================
extern "C" void kernel_launch(void* const* d_in, const int* in_sizes, int n_in,
                              void* d_out, int out_size)
{
    const float* x    = (const float*)d_in[0];
    const int*   cmap = (const int*)  d_in[1];
    const float* W1   = (const float*)d_in[2];
    const float* b1   = (const float*)d_in[3];
    const float* W2   = (const float*)d_in[4];
    const float* b2   = (const float*)d_in[5];
    const float* Wfc1 = (const float*)d_in[6];
    const float* bfc1 = (const float*)d_in[7];
    const float* Wfc2 = (const float*)d_in[8];
    const float* bfc2 = (const float*)d_in[9];
    float* out = (float*)d_out;

    cudaFuncSetAttribute(k_conv2m, cudaFuncAttributeMaxDynamicSharedMemorySize, C2_SMEM);

    k_prepf<<<72, 256>>>(W2);
    k_prep_fc1<<<8192, 256>>>(Wfc1);
    k_conv1<<<NB, 256>>>(x, cmap, W1, b1);
    k_conv2m<<<NB * 8, 128, C2_SMEM>>>(b2);
    k_fc1m<<<KSPLIT, 256>>>();
    k_fc2<<<NB, 512>>>(bfc1, Wfc2, bfc2, out);
}